// round 2
// baseline (speedup 1.0000x reference)
#include <cuda_runtime.h>
#include <cuda_bf16.h>

#define D_H 128
#define D_E 16
#define KE 273            // 2*128 + 1 + 16
#define STRIDE 131        // node_features row width
#define ETT 16            // edges (or nodes) per block tile
#define MAXN 50000

// ---- scratch (device globals: no allocation allowed) ----
__device__ float g_nbr[MAXN * D_H];     // 25.6 MB
__device__ float g_csum[MAXN * 3];
__device__ float g_cnt[MAXN];

// ---- packed f32x2 helpers ----
__device__ __forceinline__ unsigned long long pack2(float a, float b) {
    unsigned long long r;
    asm("mov.b64 %0, {%1, %2};" : "=l"(r) : "r"(__float_as_uint(a)), "r"(__float_as_uint(b)));
    return r;
}
__device__ __forceinline__ unsigned long long fma2(unsigned long long a, unsigned long long b, unsigned long long c) {
    unsigned long long d;
    asm("fma.rn.f32x2 %0, %1, %2, %3;" : "=l"(d) : "l"(a), "l"(b), "l"(c));
    return d;
}
__device__ __forceinline__ void unpack2(unsigned long long v, float& lo, float& hi) {
    unsigned int l, h;
    asm("mov.b64 {%0, %1}, %2;" : "=r"(l), "=r"(h) : "l"(v));
    lo = __uint_as_float(l); hi = __uint_as_float(h);
}
__device__ __forceinline__ float silu(float x) {
    return x / (1.0f + __expf(-x));
}

// ---- zero scratch each launch (graph replays re-run this) ----
__global__ void zero_kernel(int N) {
    int i = blockIdx.x * blockDim.x + threadIdx.x;
    int s = gridDim.x * blockDim.x;
    float4 z = make_float4(0.f, 0.f, 0.f, 0.f);
    float4* p = (float4*)g_nbr;
    int n4 = N * D_H / 4;
    for (int k = i; k < n4; k += s) p[k] = z;
    for (int k = i; k < N * 3; k += s) g_csum[k] = 0.f;
    for (int k = i; k < N; k += s) g_cnt[k] = 0.f;
}

// =====================================================================
// Edge kernel: per tile of 16 edges, compute 2-layer edge MLP (fused),
// scalar coord gate, and accumulate segment sums via atomics.
// 256 threads = 2 groups x 128. Group g handles edges [g*8, g*8+8) of the
// tile; thread j in a group computes output feature j with 8 packed-f32x2
// accumulators (one weight LDS feeds 8 MACs).
// =====================================================================
__global__ void __launch_bounds__(256, 1) edge_kernel(
    const float* __restrict__ nf, const int* __restrict__ ei, const float* __restrict__ ef,
    const float* __restrict__ We1, const float* __restrict__ be1,
    const float* __restrict__ We2, const float* __restrict__ be2,
    const float* __restrict__ Wc, const float* __restrict__ bc,
    int N, int E)
{
    extern __shared__ float sh[];
    float* sW1 = sh;                      // 273*128 = 34944
    float* sW2 = sW1 + KE * D_H;          // 128*128 = 16384
    float* sin_ = sW2 + D_H * D_H;        // 273*16  = 4368
    float* sm1 = sin_ + KE * ETT;         // 128*16  = 2048
    float* scp = sm1 + D_H * ETT;         // 8 warps * 8 = 64
    float* scd = scp + 64;                // 16*3 = 48
    int* sfi = (int*)(scd + 48);          // 16
    int* ssi = sfi + 16;                  // 16
    // total 57872 floats = 231488 B

    const int tid = threadIdx.x;
    const int j = tid & 127;              // output feature
    const int grp = tid >> 7;             // edge group 0/1
    const int g8 = grp * 8;
    const int wid = tid >> 5, lane = tid & 31;

    // stage weights
    for (int i = tid; i < KE * D_H; i += 256) sW1[i] = We1[i];
    for (int i = tid; i < D_H * D_H; i += 256) sW2[i] = We2[i];
    const float b1 = be1[j];
    const float b2 = be2[j];
    const float wcv = Wc[j];
    const float bcv = bc[0];
    __syncthreads();

    const int* first = ei;
    const int* second = ei + E;
    const int ntiles = (E + ETT - 1) / ETT;

    for (int t = blockIdx.x; t < ntiles; t += gridDim.x) {
        const int e0 = t * ETT;
        __syncthreads();  // all prior-tile smem consumers done

        // indices, coord diffs, dist2
        if (tid < ETT) {
            int e = e0 + tid;
            int fi = 0, si = 0;
            if (e < E) { fi = first[e]; si = second[e]; }
            sfi[tid] = fi; ssi[tid] = si;
            float dx = nf[fi * STRIDE + 0] - nf[si * STRIDE + 0];
            float dy = nf[fi * STRIDE + 1] - nf[si * STRIDE + 1];
            float dz = nf[fi * STRIDE + 2] - nf[si * STRIDE + 2];
            scd[tid * 3 + 0] = dx; scd[tid * 3 + 1] = dy; scd[tid * 3 + 2] = dz;
            sin_[256 * ETT + tid] = dx * dx + dy * dy + dz * dz;
        }
        // edge features: 256 threads = 16 edges x 16 feats
        {
            int e = tid >> 4, f = tid & 15;
            int ee = e0 + e;
            sin_[(257 + f) * ETT + e] = (ee < E) ? ef[ee * D_E + f] : 0.f;
        }
        __syncthreads();

        // gather h[first], h[second] (L2-resident after first wave)
        #pragma unroll
        for (int e = 0; e < 8; e++) {
            int s = g8 + e;
            int fi = sfi[s], si = ssi[s];
            sin_[j * ETT + s] = nf[fi * STRIDE + 3 + j];
            sin_[(D_H + j) * ETT + s] = nf[si * STRIDE + 3 + j];
        }
        __syncthreads();

        // ---- layer 1: 273 x 128 ----
        unsigned long long a0 = pack2(b1, b1), a1 = a0, a2 = a0, a3 = a0;
        {
            const float* wcol = sW1 + j;
            const float* ib = sin_ + g8;
            #pragma unroll 3
            for (int k = 0; k < KE; k++) {
                float w = wcol[k * D_H];
                unsigned long long w2 = pack2(w, w);
                const ulonglong2* ip = (const ulonglong2*)(ib + k * ETT);
                ulonglong2 q = ip[0];
                a0 = fma2(q.x, w2, a0);
                a1 = fma2(q.y, w2, a1);
                ulonglong2 r = ip[1];
                a2 = fma2(r.x, w2, a2);
                a3 = fma2(r.y, w2, a3);
            }
        }
        {
            float v[8];
            unpack2(a0, v[0], v[1]); unpack2(a1, v[2], v[3]);
            unpack2(a2, v[4], v[5]); unpack2(a3, v[6], v[7]);
            #pragma unroll
            for (int e = 0; e < 8; e++) v[e] = silu(v[e]);
            float4* r4 = (float4*)(sm1 + j * ETT + g8);
            r4[0] = make_float4(v[0], v[1], v[2], v[3]);
            r4[1] = make_float4(v[4], v[5], v[6], v[7]);
        }
        __syncthreads();

        // ---- layer 2: 128 x 128 ----
        unsigned long long c0 = pack2(b2, b2), c1 = c0, c2 = c0, c3 = c0;
        {
            const float* wcol = sW2 + j;
            const float* ib = sm1 + g8;
            #pragma unroll 4
            for (int k = 0; k < D_H; k++) {
                float w = wcol[k * D_H];
                unsigned long long w2 = pack2(w, w);
                const ulonglong2* ip = (const ulonglong2*)(ib + k * ETT);
                ulonglong2 q = ip[0];
                c0 = fma2(q.x, w2, c0);
                c1 = fma2(q.y, w2, c1);
                ulonglong2 r = ip[1];
                c2 = fma2(r.x, w2, c2);
                c3 = fma2(r.y, w2, c3);
            }
        }
        float mv[8];
        unpack2(c0, mv[0], mv[1]); unpack2(c1, mv[2], mv[3]);
        unpack2(c2, mv[4], mv[5]); unpack2(c3, mv[6], mv[7]);
        #pragma unroll
        for (int e = 0; e < 8; e++) mv[e] = silu(mv[e]);

        // ---- coord gate: c[e] = bc + sum_j m[j][e]*Wc[j] ----
        {
            float p[8];
            #pragma unroll
            for (int e = 0; e < 8; e++) p[e] = mv[e] * wcv;
            #pragma unroll
            for (int off = 16; off > 0; off >>= 1) {
                #pragma unroll
                for (int e = 0; e < 8; e++) p[e] += __shfl_xor_sync(0xffffffffu, p[e], off);
            }
            if (lane == 0) {
                #pragma unroll
                for (int e = 0; e < 8; e++) scp[wid * 8 + e] = p[e];
            }
        }
        __syncthreads();

        // coord + count atomics (one lane per edge slot)
        if (tid < ETT && (e0 + tid) < E) {
            int g = tid >> 3, el = tid & 7;
            float c = bcv + scp[(g * 4 + 0) * 8 + el] + scp[(g * 4 + 1) * 8 + el]
                          + scp[(g * 4 + 2) * 8 + el] + scp[(g * 4 + 3) * 8 + el];
            int fi = sfi[tid];
            atomicAdd(&g_csum[fi * 3 + 0], scd[tid * 3 + 0] * c);
            atomicAdd(&g_csum[fi * 3 + 1], scd[tid * 3 + 1] * c);
            atomicAdd(&g_csum[fi * 3 + 2], scd[tid * 3 + 2] * c);
            atomicAdd(&g_cnt[fi], 1.0f);
        }

        // nbr_sum atomics: coalesced per edge across the 128 feature lanes
        #pragma unroll
        for (int e = 0; e < 8; e++) {
            int s = g8 + e;
            if (e0 + s < E) atomicAdd(&g_nbr[sfi[s] * D_H + j], mv[e]);
        }
    }
}

// =====================================================================
// Node kernel: 2-layer node MLP + coord update + output packing.
// Same structure: 16 contiguous nodes per tile.
// =====================================================================
__global__ void __launch_bounds__(256, 1) node_kernel(
    const float* __restrict__ nf,
    const float* __restrict__ Wn1, const float* __restrict__ bn1,
    const float* __restrict__ Wn2, const float* __restrict__ bn2,
    float* __restrict__ out, int N)
{
    extern __shared__ float sh[];
    float* sW1 = sh;                      // 256*128 = 32768
    float* sW2 = sW1 + 256 * D_H;         // 16384
    float* sin_ = sW2 + D_H * D_H;        // 256*16 = 4096
    float* st1 = sin_ + 256 * ETT;        // 128*16 = 2048
    // total 55296 floats = 221184 B

    const int tid = threadIdx.x;
    const int j = tid & 127;
    const int grp = tid >> 7;
    const int g8 = grp * 8;

    for (int i = tid; i < 256 * D_H; i += 256) sW1[i] = Wn1[i];
    for (int i = tid; i < D_H * D_H; i += 256) sW2[i] = Wn2[i];
    const float b1 = bn1[j];
    const float b2 = bn2[j];
    __syncthreads();

    const int ntiles = (N + ETT - 1) / ETT;

    for (int t = blockIdx.x; t < ntiles; t += gridDim.x) {
        const int n0 = t * ETT;
        __syncthreads();

        #pragma unroll
        for (int e = 0; e < 8; e++) {
            int s = g8 + e;
            int n = n0 + s; if (n >= N) n = N - 1;
            sin_[j * ETT + s] = nf[n * STRIDE + 3 + j];
            sin_[(D_H + j) * ETT + s] = g_nbr[n * D_H + j];
        }
        __syncthreads();

        // layer 1: 256 x 128, silu
        unsigned long long a0 = pack2(b1, b1), a1 = a0, a2 = a0, a3 = a0;
        {
            const float* wcol = sW1 + j;
            const float* ib = sin_ + g8;
            #pragma unroll 4
            for (int k = 0; k < 256; k++) {
                float w = wcol[k * D_H];
                unsigned long long w2 = pack2(w, w);
                const ulonglong2* ip = (const ulonglong2*)(ib + k * ETT);
                ulonglong2 q = ip[0];
                a0 = fma2(q.x, w2, a0);
                a1 = fma2(q.y, w2, a1);
                ulonglong2 r = ip[1];
                a2 = fma2(r.x, w2, a2);
                a3 = fma2(r.y, w2, a3);
            }
        }
        {
            float v[8];
            unpack2(a0, v[0], v[1]); unpack2(a1, v[2], v[3]);
            unpack2(a2, v[4], v[5]); unpack2(a3, v[6], v[7]);
            #pragma unroll
            for (int e = 0; e < 8; e++) v[e] = silu(v[e]);
            float4* r4 = (float4*)(st1 + j * ETT + g8);
            r4[0] = make_float4(v[0], v[1], v[2], v[3]);
            r4[1] = make_float4(v[4], v[5], v[6], v[7]);
        }
        __syncthreads();

        // layer 2: 128 x 128, no activation
        unsigned long long c0 = pack2(b2, b2), c1 = c0, c2 = c0, c3 = c0;
        {
            const float* wcol = sW2 + j;
            const float* ib = st1 + g8;
            #pragma unroll 4
            for (int k = 0; k < D_H; k++) {
                float w = wcol[k * D_H];
                unsigned long long w2 = pack2(w, w);
                const ulonglong2* ip = (const ulonglong2*)(ib + k * ETT);
                ulonglong2 q = ip[0];
                c0 = fma2(q.x, w2, c0);
                c1 = fma2(q.y, w2, c1);
                ulonglong2 r = ip[1];
                c2 = fma2(r.x, w2, c2);
                c3 = fma2(r.y, w2, c3);
            }
        }
        float v[8];
        unpack2(c0, v[0], v[1]); unpack2(c1, v[2], v[3]);
        unpack2(c2, v[4], v[5]); unpack2(c3, v[6], v[7]);
        #pragma unroll
        for (int e = 0; e < 8; e++) {
            int n = n0 + g8 + e;
            if (n < N) out[n * STRIDE + 3 + j] = v[e];
        }

        // coords output
        if (tid < ETT) {
            int n = n0 + tid;
            if (n < N) {
                float cnt = fmaxf(g_cnt[n], 1.0f);
                float inv = 1.0f / cnt;
                out[n * STRIDE + 0] = nf[n * STRIDE + 0] + g_csum[n * 3 + 0] * inv;
                out[n * STRIDE + 1] = nf[n * STRIDE + 1] + g_csum[n * 3 + 1] * inv;
                out[n * STRIDE + 2] = nf[n * STRIDE + 2] + g_csum[n * 3 + 2] * inv;
            }
        }
    }
}

// =====================================================================
extern "C" void kernel_launch(void* const* d_in, const int* in_sizes, int n_in,
                              void* d_out, int out_size) {
    const float* nf  = (const float*)d_in[0];
    const int*   ei  = (const int*)d_in[1];
    const float* ef  = (const float*)d_in[2];
    const float* We1 = (const float*)d_in[3];
    const float* be1 = (const float*)d_in[4];
    const float* We2 = (const float*)d_in[5];
    const float* be2 = (const float*)d_in[6];
    const float* Wc  = (const float*)d_in[7];
    const float* bc  = (const float*)d_in[8];
    const float* Wn1 = (const float*)d_in[9];
    const float* bn1 = (const float*)d_in[10];
    const float* Wn2 = (const float*)d_in[11];
    const float* bn2 = (const float*)d_in[12];
    float* out = (float*)d_out;

    const int N = in_sizes[0] / STRIDE;
    const int E = in_sizes[2] / D_E;

    const int EDGE_SMEM = 57872 * 4;   // 231488 B
    const int NODE_SMEM = 55296 * 4;   // 221184 B
    cudaFuncSetAttribute(edge_kernel, cudaFuncAttributeMaxDynamicSharedMemorySize, EDGE_SMEM);
    cudaFuncSetAttribute(node_kernel, cudaFuncAttributeMaxDynamicSharedMemorySize, NODE_SMEM);

    zero_kernel<<<1024, 256>>>(N);
    edge_kernel<<<148, 256, EDGE_SMEM>>>(nf, ei, ef, We1, be1, We2, be2, Wc, bc, N, E);
    node_kernel<<<148, 256, NODE_SMEM>>>(nf, Wn1, bn1, Wn2, bn2, out, N);
}

// round 4
// speedup vs baseline: 1.0844x; 1.0844x over previous
#include <cuda_runtime.h>

#define D_H 128
#define D_E 16
#define KE 273            // 2*128 + 1 + 16
#define STRIDE 131
#define ETT 32            // edges per block tile (edge kernel)
#define CH 28             // layer-1 chunk rows
#define NCH 10            // ceil(256/28)
#define NTT 16            // nodes per tile (node kernel)
#define MAXN 50000

// ---- scratch (device globals: no allocation allowed) ----
__device__ float g_nbr[MAXN * D_H];
__device__ float g_csum[MAXN * 3];
__device__ float g_cnt[MAXN];

typedef unsigned long long ull;

__device__ __forceinline__ ull pack2(float a, float b) {
    ull r; asm("mov.b64 %0, {%1, %2};" : "=l"(r) : "r"(__float_as_uint(a)), "r"(__float_as_uint(b)));
    return r;
}
__device__ __forceinline__ ull fma2(ull a, ull b, ull c) {
    ull d; asm("fma.rn.f32x2 %0, %1, %2, %3;" : "=l"(d) : "l"(a), "l"(b), "l"(c));
    return d;
}
__device__ __forceinline__ void unpack2(ull v, float& lo, float& hi) {
    unsigned l, h; asm("mov.b64 {%0, %1}, %2;" : "=r"(l), "=r"(h) : "l"(v));
    lo = __uint_as_float(l); hi = __uint_as_float(h);
}
__device__ __forceinline__ float silu(float x) { return x / (1.0f + __expf(-x)); }

__device__ __forceinline__ void cpa4(unsigned dst, const float* src) {
    asm volatile("cp.async.ca.shared.global [%0], [%1], 4;" :: "r"(dst), "l"(src));
}

// 8 FMA2 per k-step: 2 j's (w2a/w2b) x 8 edges (4 f32x2 pairs)
__device__ __forceinline__ void step8(const float* __restrict__ w, const float* __restrict__ x, ull* a) {
    float2 wv = *(const float2*)w;
    ull w0 = pack2(wv.x, wv.x), w1 = pack2(wv.y, wv.y);
    ulonglong2 q = ((const ulonglong2*)x)[0];
    a[0] = fma2(q.x, w0, a[0]); a[4] = fma2(q.x, w1, a[4]);
    a[1] = fma2(q.y, w0, a[1]); a[5] = fma2(q.y, w1, a[5]);
    ulonglong2 r = ((const ulonglong2*)x)[1];
    a[2] = fma2(r.x, w0, a[2]); a[6] = fma2(r.x, w1, a[6]);
    a[3] = fma2(r.y, w0, a[3]); a[7] = fma2(r.y, w1, a[7]);
}

// ---- zero scratch each launch ----
__global__ void zero_kernel(int N) {
    int i = blockIdx.x * blockDim.x + threadIdx.x;
    int s = gridDim.x * blockDim.x;
    float4 z = make_float4(0.f, 0.f, 0.f, 0.f);
    float4* p = (float4*)g_nbr;
    int n4 = N * D_H / 4;
    for (int k = i; k < n4; k += s) p[k] = z;
    for (int k = i; k < N * 3; k += s) g_csum[k] = 0.f;
    for (int k = i; k < N; k += s) g_cnt[k] = 0.f;
}

// =====================================================================
// Edge kernel: 32-edge tiles. 256 threads = 4 edge-sets x 64 j-pair
// threads. Layer-1 inputs staged in 28-row chunks, double-buffered via
// cp.async so gathers overlap the FMA loop. Accumulators live across
// chunks. Atomic segment sums into device-global scratch.
// =====================================================================
__global__ void __launch_bounds__(256, 1) edge_kernel(
    const float* __restrict__ nf, const int* __restrict__ ei, const float* __restrict__ ef,
    const float* __restrict__ We1, const float* __restrict__ be1,
    const float* __restrict__ We2, const float* __restrict__ be2,
    const float* __restrict__ Wc, const float* __restrict__ bc,
    int N, int E)
{
    extern __shared__ float sh[];
    float* sW1 = sh;                       // 273*128 = 34944
    float* sW2 = sW1 + KE * D_H;           // 16384
    float* sm1 = sW2 + D_H * D_H;          // 128*32 = 4096
    float* sch = sm1 + D_H * ETT;          // 2*28*32 = 1792
    float* sde = sch + 2 * CH * ETT;       // 17*32 = 544 (row0=dist2, rows1-16=ef)
    float* scd = sde + 17 * ETT;           // 3*32 = 96
    float* scp = scd + 3 * ETT;            // 64
    int* sfi = (int*)(scp + 64);           // 32
    int* ssi = sfi + ETT;                  // 32
    // total 57984 floats = 231936 B

    const int tid = threadIdx.x;
    const int lane = tid & 31, wid = tid >> 5;
    const int j6 = tid & 63;               // j-pair index
    const int s = tid >> 6;                // edge set 0..3
    const int j0 = 2 * j6;
    const int x8 = 8 * s;

    // stage weights (vectorized)
    {
        const float4* a = (const float4*)We1; float4* d = (float4*)sW1;
        for (int i = tid; i < KE * D_H / 4; i += 256) d[i] = a[i];
        const float4* b = (const float4*)We2; float4* d2 = (float4*)sW2;
        for (int i = tid; i < D_H * D_H / 4; i += 256) d2[i] = b[i];
    }
    const float b1a = be1[j0], b1b = be1[j0 + 1];
    const float b2a = be2[j0], b2b = be2[j0 + 1];
    const float wc0 = Wc[j0], wc1 = Wc[j0 + 1];
    const float bcv = bc[0];
    __syncthreads();

    const int* first = ei;
    const int* second = ei + E;
    const int ntiles = (E + ETT - 1) / ETT;
    const unsigned sch_u = (unsigned)__cvta_generic_to_shared(sch);

    for (int t = blockIdx.x; t < ntiles; t += gridDim.x) {
        const int e0 = t * ETT;
        __syncthreads();   // protect sfi/scd/sde/scp from prior-tile consumers

        // ---- stage A: indices, coord diffs, dist2, edge features ----
        if (tid < ETT) {
            int e = e0 + tid;
            int fi = 0, si = 0;
            if (e < E) { fi = first[e]; si = second[e]; }
            sfi[tid] = fi; ssi[tid] = si;
            float dx = nf[fi * STRIDE + 0] - nf[si * STRIDE + 0];
            float dy = nf[fi * STRIDE + 1] - nf[si * STRIDE + 1];
            float dz = nf[fi * STRIDE + 2] - nf[si * STRIDE + 2];
            scd[0 * ETT + tid] = dx; scd[1 * ETT + tid] = dy; scd[2 * ETT + tid] = dz;
            sde[tid] = dx * dx + dy * dy + dz * dz;
        }
        for (int idx = tid; idx < D_E * ETT; idx += 256) {
            int f = idx >> 5, e = idx & 31;
            int ee = e0 + e;
            sde[(1 + f) * ETT + e] = (ee < E) ? ef[ee * D_E + f] : 0.f;
        }
        __syncthreads();

        // ---- stage chunk 0 via cp.async ----
        for (int idx = tid; idx < CH * ETT; idx += 256) {
            int r = idx >> 5, e = idx & 31;          // global row g = r
            const float* src = nf + sfi[e] * STRIDE + 3 + r;
            cpa4(sch_u + (unsigned)(idx * 4), src);
        }
        asm volatile("cp.async.commit_group;" ::: "memory");

        ull acc[8];
        acc[0] = acc[1] = acc[2] = acc[3] = pack2(b1a, b1a);
        acc[4] = acc[5] = acc[6] = acc[7] = pack2(b1b, b1b);

        // ---- layer 1 over chunked inputs, pipelined ----
        for (int c = 0; c < NCH; c++) {
            if (c + 1 < NCH) {
                int k0n = (c + 1) * CH;
                int Rn = min(CH, 256 - k0n);
                unsigned base = sch_u + (unsigned)((((c + 1) & 1) * CH * ETT) * 4);
                for (int idx = tid; idx < Rn * ETT; idx += 256) {
                    int r = idx >> 5, e = idx & 31;
                    int g = k0n + r;
                    const float* src = (g < 128) ? (nf + sfi[e] * STRIDE + 3 + g)
                                                 : (nf + ssi[e] * STRIDE + 3 + (g - 128));
                    cpa4(base + (unsigned)(idx * 4), src);
                }
                asm volatile("cp.async.commit_group;" ::: "memory");
                asm volatile("cp.async.wait_group 1;" ::: "memory");
            } else {
                asm volatile("cp.async.wait_group 0;" ::: "memory");
            }
            __syncthreads();   // chunk c visible to all

            const int k0 = c * CH;
            const int R = min(CH, 256 - k0);
            const float* wrow = sW1 + k0 * D_H + j0;
            const float* xrow = sch + (c & 1) * CH * ETT + x8;
            #pragma unroll 4
            for (int r = 0; r < R; r++) {
                step8(wrow, xrow, acc);
                wrow += D_H; xrow += ETT;
            }
            __syncthreads();   // done reading this buffer before restage
        }
        // epilogue rows 256..272: dist2 + edge features
        {
            const float* wrow = sW1 + 256 * D_H + j0;
            const float* xrow = sde + x8;
            #pragma unroll 4
            for (int r = 0; r < 17; r++) {
                step8(wrow, xrow, acc);
                wrow += D_H; xrow += ETT;
            }
        }

        // ---- silu + write m1 tile ----
        {
            float v0[8], v1[8];
            unpack2(acc[0], v0[0], v0[1]); unpack2(acc[1], v0[2], v0[3]);
            unpack2(acc[2], v0[4], v0[5]); unpack2(acc[3], v0[6], v0[7]);
            unpack2(acc[4], v1[0], v1[1]); unpack2(acc[5], v1[2], v1[3]);
            unpack2(acc[6], v1[4], v1[5]); unpack2(acc[7], v1[6], v1[7]);
            #pragma unroll
            for (int e = 0; e < 8; e++) { v0[e] = silu(v0[e]); v1[e] = silu(v1[e]); }
            float4* r0 = (float4*)(sm1 + (j0 + 0) * ETT + x8);
            r0[0] = make_float4(v0[0], v0[1], v0[2], v0[3]);
            r0[1] = make_float4(v0[4], v0[5], v0[6], v0[7]);
            float4* r1 = (float4*)(sm1 + (j0 + 1) * ETT + x8);
            r1[0] = make_float4(v1[0], v1[1], v1[2], v1[3]);
            r1[1] = make_float4(v1[4], v1[5], v1[6], v1[7]);
        }
        __syncthreads();

        // ---- layer 2 ----
        ull a2[8];
        a2[0] = a2[1] = a2[2] = a2[3] = pack2(b2a, b2a);
        a2[4] = a2[5] = a2[6] = a2[7] = pack2(b2b, b2b);
        {
            const float* wrow = sW2 + j0;
            const float* xrow = sm1 + x8;
            #pragma unroll 4
            for (int k = 0; k < D_H; k++) {
                step8(wrow, xrow, a2);
                wrow += D_H; xrow += ETT;
            }
        }
        float m0[8], m1v[8];
        unpack2(a2[0], m0[0], m0[1]); unpack2(a2[1], m0[2], m0[3]);
        unpack2(a2[2], m0[4], m0[5]); unpack2(a2[3], m0[6], m0[7]);
        unpack2(a2[4], m1v[0], m1v[1]); unpack2(a2[5], m1v[2], m1v[3]);
        unpack2(a2[6], m1v[4], m1v[5]); unpack2(a2[7], m1v[6], m1v[7]);
        #pragma unroll
        for (int e = 0; e < 8; e++) { m0[e] = silu(m0[e]); m1v[e] = silu(m1v[e]); }

        // ---- coord gate reduction over j ----
        {
            float cs[8];
            #pragma unroll
            for (int e = 0; e < 8; e++) cs[e] = m0[e] * wc0 + m1v[e] * wc1;
            #pragma unroll
            for (int off = 16; off > 0; off >>= 1) {
                #pragma unroll
                for (int e = 0; e < 8; e++) cs[e] += __shfl_xor_sync(0xffffffffu, cs[e], off);
            }
            if (lane == 0) {
                #pragma unroll
                for (int e = 0; e < 8; e++) scp[wid * 8 + e] = cs[e];
            }
        }
        __syncthreads();

        // ---- coord + count atomics ----
        if (tid < ETT && (e0 + tid) < E) {
            int s2 = tid >> 3, el = tid & 7;
            float c = bcv + scp[(2 * s2) * 8 + el] + scp[(2 * s2 + 1) * 8 + el];
            int fi = sfi[tid];
            atomicAdd(&g_csum[fi * 3 + 0], scd[0 * ETT + tid] * c);
            atomicAdd(&g_csum[fi * 3 + 1], scd[1 * ETT + tid] * c);
            atomicAdd(&g_csum[fi * 3 + 2], scd[2 * ETT + tid] * c);
            atomicAdd(&g_cnt[fi], 1.0f);
        }

        // ---- nbr_sum atomics (coalesced across j) ----
        #pragma unroll
        for (int e = 0; e < 8; e++) {
            int slot = x8 + e;
            if (e0 + slot < E) {
                int fi = sfi[slot];
                atomicAdd(&g_nbr[fi * D_H + j0], m0[e]);
                atomicAdd(&g_nbr[fi * D_H + j0 + 1], m1v[e]);
            }
        }
    }
}

// =====================================================================
// Node kernel: unchanged from the passing round-2 version (16-node tiles)
// =====================================================================
__global__ void __launch_bounds__(256, 1) node_kernel(
    const float* __restrict__ nf,
    const float* __restrict__ Wn1, const float* __restrict__ bn1,
    const float* __restrict__ Wn2, const float* __restrict__ bn2,
    float* __restrict__ out, int N)
{
    extern __shared__ float sh[];
    float* sW1 = sh;                      // 256*128 = 32768
    float* sW2 = sW1 + 256 * D_H;         // 16384
    float* sin_ = sW2 + D_H * D_H;        // 256*16 = 4096
    float* st1 = sin_ + 256 * NTT;        // 128*16 = 2048
    // total 55296 floats = 221184 B

    const int tid = threadIdx.x;
    const int j = tid & 127;
    const int grp = tid >> 7;
    const int g8 = grp * 8;

    for (int i = tid; i < 256 * D_H; i += 256) sW1[i] = Wn1[i];
    for (int i = tid; i < D_H * D_H; i += 256) sW2[i] = Wn2[i];
    const float b1 = bn1[j];
    const float b2 = bn2[j];
    __syncthreads();

    const int ntiles = (N + NTT - 1) / NTT;

    for (int t = blockIdx.x; t < ntiles; t += gridDim.x) {
        const int n0 = t * NTT;
        __syncthreads();

        #pragma unroll
        for (int e = 0; e < 8; e++) {
            int s = g8 + e;
            int n = n0 + s; if (n >= N) n = N - 1;
            sin_[j * NTT + s] = nf[n * STRIDE + 3 + j];
            sin_[(D_H + j) * NTT + s] = g_nbr[n * D_H + j];
        }
        __syncthreads();

        ull a0 = pack2(b1, b1), a1 = a0, a2 = a0, a3 = a0;
        {
            const float* wcol = sW1 + j;
            const float* ib = sin_ + g8;
            #pragma unroll 4
            for (int k = 0; k < 256; k++) {
                float w = wcol[k * D_H];
                ull w2 = pack2(w, w);
                const ulonglong2* ip = (const ulonglong2*)(ib + k * NTT);
                ulonglong2 q = ip[0];
                a0 = fma2(q.x, w2, a0);
                a1 = fma2(q.y, w2, a1);
                ulonglong2 r = ip[1];
                a2 = fma2(r.x, w2, a2);
                a3 = fma2(r.y, w2, a3);
            }
        }
        {
            float v[8];
            unpack2(a0, v[0], v[1]); unpack2(a1, v[2], v[3]);
            unpack2(a2, v[4], v[5]); unpack2(a3, v[6], v[7]);
            #pragma unroll
            for (int e = 0; e < 8; e++) v[e] = silu(v[e]);
            float4* r4 = (float4*)(st1 + j * NTT + g8);
            r4[0] = make_float4(v[0], v[1], v[2], v[3]);
            r4[1] = make_float4(v[4], v[5], v[6], v[7]);
        }
        __syncthreads();

        ull c0 = pack2(b2, b2), c1 = c0, c2 = c0, c3 = c0;
        {
            const float* wcol = sW2 + j;
            const float* ib = st1 + g8;
            #pragma unroll 4
            for (int k = 0; k < D_H; k++) {
                float w = wcol[k * D_H];
                ull w2 = pack2(w, w);
                const ulonglong2* ip = (const ulonglong2*)(ib + k * NTT);
                ulonglong2 q = ip[0];
                c0 = fma2(q.x, w2, c0);
                c1 = fma2(q.y, w2, c1);
                ulonglong2 r = ip[1];
                c2 = fma2(r.x, w2, c2);
                c3 = fma2(r.y, w2, c3);
            }
        }
        float v[8];
        unpack2(c0, v[0], v[1]); unpack2(c1, v[2], v[3]);
        unpack2(c2, v[4], v[5]); unpack2(c3, v[6], v[7]);
        #pragma unroll
        for (int e = 0; e < 8; e++) {
            int n = n0 + g8 + e;
            if (n < N) out[n * STRIDE + 3 + j] = v[e];
        }

        if (tid < NTT) {
            int n = n0 + tid;
            if (n < N) {
                float cnt = fmaxf(g_cnt[n], 1.0f);
                float inv = 1.0f / cnt;
                out[n * STRIDE + 0] = nf[n * STRIDE + 0] + g_csum[n * 3 + 0] * inv;
                out[n * STRIDE + 1] = nf[n * STRIDE + 1] + g_csum[n * 3 + 1] * inv;
                out[n * STRIDE + 2] = nf[n * STRIDE + 2] + g_csum[n * 3 + 2] * inv;
            }
        }
    }
}

// =====================================================================
extern "C" void kernel_launch(void* const* d_in, const int* in_sizes, int n_in,
                              void* d_out, int out_size) {
    const float* nf  = (const float*)d_in[0];
    const int*   ei  = (const int*)d_in[1];
    const float* ef  = (const float*)d_in[2];
    const float* We1 = (const float*)d_in[3];
    const float* be1 = (const float*)d_in[4];
    const float* We2 = (const float*)d_in[5];
    const float* be2 = (const float*)d_in[6];
    const float* Wc  = (const float*)d_in[7];
    const float* bc  = (const float*)d_in[8];
    const float* Wn1 = (const float*)d_in[9];
    const float* bn1 = (const float*)d_in[10];
    const float* Wn2 = (const float*)d_in[11];
    const float* bn2 = (const float*)d_in[12];
    float* out = (float*)d_out;

    const int N = in_sizes[0] / STRIDE;
    const int E = in_sizes[2] / D_E;

    const int EDGE_SMEM = 57984 * 4;   // 231936 B
    const int NODE_SMEM = 55296 * 4;   // 221184 B
    cudaFuncSetAttribute(edge_kernel, cudaFuncAttributeMaxDynamicSharedMemorySize, EDGE_SMEM);
    cudaFuncSetAttribute(node_kernel, cudaFuncAttributeMaxDynamicSharedMemorySize, NODE_SMEM);

    zero_kernel<<<1024, 256>>>(N);
    edge_kernel<<<148, 256, EDGE_SMEM>>>(nf, ei, ef, We1, be1, We2, be2, Wc, bc, N, E);
    node_kernel<<<148, 256, NODE_SMEM>>>(nf, Wn1, bn1, Wn2, bn2, out, N);
}

// round 6
// speedup vs baseline: 1.3904x; 1.2821x over previous
#include <cuda_runtime.h>

#define D_H 128
#define D_E 16
#define KE 273            // 2*128 + 1 + 16
#define STRIDE 131
#define ETT 64            // edges per block tile (edge kernel)
#define CH 32             // chunk rows (weights + inputs), 256/32 = 8 chunks
#define NCH 8
#define TPB 512
#define NTT 16            // nodes per tile (node kernel)
#define MAXN 50000

// ---- scratch (device globals: no allocation allowed) ----
__device__ float g_nbr[MAXN * D_H];
__device__ float g_csum[MAXN * 3];
__device__ float g_cnt[MAXN];

typedef unsigned long long ull;

__device__ __forceinline__ ull pack2(float a, float b) {
    ull r; asm("mov.b64 %0, {%1, %2};" : "=l"(r) : "r"(__float_as_uint(a)), "r"(__float_as_uint(b)));
    return r;
}
__device__ __forceinline__ ull fma2(ull a, ull b, ull c) {
    ull d; asm("fma.rn.f32x2 %0, %1, %2, %3;" : "=l"(d) : "l"(a), "l"(b), "l"(c));
    return d;
}
__device__ __forceinline__ void unpack2(ull v, float& lo, float& hi) {
    unsigned l, h; asm("mov.b64 {%0, %1}, %2;" : "=r"(l), "=r"(h) : "l"(v));
    lo = __uint_as_float(l); hi = __uint_as_float(h);
}
__device__ __forceinline__ float silu(float x) { return x / (1.0f + __expf(-x)); }

__device__ __forceinline__ void cpa4(unsigned dst, const float* src) {
    asm volatile("cp.async.ca.shared.global [%0], [%1], 4;" :: "r"(dst), "l"(src));
}
__device__ __forceinline__ void cpa16(unsigned dst, const float* src) {
    asm volatile("cp.async.ca.shared.global [%0], [%1], 16;" :: "r"(dst), "l"(src));
}

// 8 FMA2 per k-step: 2 j's x 8 edges (4 f32x2 pairs)
__device__ __forceinline__ void step8(const float* __restrict__ w, const float* __restrict__ x, ull* a) {
    float2 wv = *(const float2*)w;
    ull w0 = pack2(wv.x, wv.x), w1 = pack2(wv.y, wv.y);
    ulonglong2 q = ((const ulonglong2*)x)[0];
    a[0] = fma2(q.x, w0, a[0]); a[4] = fma2(q.x, w1, a[4]);
    a[1] = fma2(q.y, w0, a[1]); a[5] = fma2(q.y, w1, a[5]);
    ulonglong2 r = ((const ulonglong2*)x)[1];
    a[2] = fma2(r.x, w0, a[2]); a[6] = fma2(r.x, w1, a[6]);
    a[3] = fma2(r.y, w0, a[3]); a[7] = fma2(r.y, w1, a[7]);
}

// ---- zero scratch each launch ----
__global__ void zero_kernel(int N) {
    int i = blockIdx.x * blockDim.x + threadIdx.x;
    int s = gridDim.x * blockDim.x;
    float4 z = make_float4(0.f, 0.f, 0.f, 0.f);
    float4* p = (float4*)g_nbr;
    int n4 = N * D_H / 4;
    for (int k = i; k < n4; k += s) p[k] = z;
    for (int k = i; k < N * 3; k += s) g_csum[k] = 0.f;
    for (int k = i; k < N; k += s) g_cnt[k] = 0.f;
}

// =====================================================================
// Edge kernel: 64-edge tiles, 512 threads = 8 edge-sets x 64 j-pairs.
// We1 streamed in 32-row chunks (weights 16KB + inputs 8KB per chunk),
// double-buffered via cp.async. W2 + epilogue weights resident in smem.
// 162KB smem -> 4 warps/SMSP for latency hiding.
// =====================================================================
__global__ void __launch_bounds__(TPB, 1) edge_kernel(
    const float* __restrict__ nf, const int* __restrict__ ei, const float* __restrict__ ef,
    const float* __restrict__ We1, const float* __restrict__ be1,
    const float* __restrict__ We2, const float* __restrict__ be2,
    const float* __restrict__ Wc, const float* __restrict__ bc,
    int N, int E)
{
    extern __shared__ float sh[];
    float* sW2 = sh;                        // 128*128 = 16384
    float* sm1 = sW2 + D_H * D_H;           // 128*64  = 8192
    float* swc = sm1 + D_H * ETT;           // 2*32*128 = 8192 (weight chunks)
    float* sic = swc + 2 * CH * D_H;        // 2*32*64 = 4096 (input chunks)
    float* sWe = sic + 2 * CH * ETT;        // 17*128 = 2176 (epilogue weights)
    float* sde = sWe + 17 * D_H;            // 17*64 = 1088 (dist2 + edge feats)
    float* scd = sde + 17 * ETT;            // 3*64 = 192
    float* scp = scd + 3 * ETT;             // 16 warps * 8 = 128
    int* sfi = (int*)(scp + 128);           // 64
    int* ssi = sfi + ETT;                   // 64
    // total 40576 floats = 162304 B

    const int tid = threadIdx.x;
    const int lane = tid & 31, wid = tid >> 5;
    const int j6 = tid & 63;                // j-pair index
    const int s = tid >> 6;                 // edge set 0..7
    const int j0 = 2 * j6;
    const int x8 = 8 * s;

    // stage resident weights: W2 and We1 rows 256..272
    {
        const float4* b = (const float4*)We2; float4* d2 = (float4*)sW2;
        for (int i = tid; i < D_H * D_H / 4; i += TPB) d2[i] = b[i];
        const float4* e4 = (const float4*)(We1 + 256 * D_H); float4* d3 = (float4*)sWe;
        for (int i = tid; i < 17 * D_H / 4; i += TPB) d3[i] = e4[i];
    }
    const float b1a = be1[j0], b1b = be1[j0 + 1];
    const float b2a = be2[j0], b2b = be2[j0 + 1];
    const float wc0 = Wc[j0], wc1 = Wc[j0 + 1];
    const float bcv = bc[0];
    __syncthreads();

    const int* first = ei;
    const int* second = ei + E;
    const int ntiles = (E + ETT - 1) / ETT;
    const unsigned swc_u = (unsigned)__cvta_generic_to_shared(swc);
    const unsigned sic_u = (unsigned)__cvta_generic_to_shared(sic);

    for (int t = blockIdx.x; t < ntiles; t += gridDim.x) {
        const int e0 = t * ETT;
        __syncthreads();   // protect per-tile smem from prior-tile consumers

        // ---- stage A: indices, coord diffs, dist2, edge features ----
        if (tid < ETT) {
            int e = e0 + tid;
            int fi = 0, si = 0;
            if (e < E) { fi = first[e]; si = second[e]; }
            sfi[tid] = fi; ssi[tid] = si;
            float dx = nf[fi * STRIDE + 0] - nf[si * STRIDE + 0];
            float dy = nf[fi * STRIDE + 1] - nf[si * STRIDE + 1];
            float dz = nf[fi * STRIDE + 2] - nf[si * STRIDE + 2];
            scd[0 * ETT + tid] = dx; scd[1 * ETT + tid] = dy; scd[2 * ETT + tid] = dz;
            sde[tid] = dx * dx + dy * dy + dz * dz;
        }
        for (int idx = tid; idx < D_E * ETT; idx += TPB) {
            int f = idx >> 6, e = idx & 63;
            int ee = e0 + e;
            sde[(1 + f) * ETT + e] = (ee < E) ? ef[ee * D_E + f] : 0.f;
        }
        __syncthreads();   // sfi/ssi visible before gathers

        // ---- stage chunk 0 (weights 16B + inputs 4B) ----
        {
            for (int i = tid; i < CH * D_H / 4; i += TPB)
                cpa16(swc_u + (unsigned)(i * 16), We1 + i * 4);
            for (int idx = tid; idx < CH * ETT; idx += TPB) {
                int r = idx >> 6, e = idx & 63;
                cpa4(sic_u + (unsigned)(idx * 4), nf + sfi[e] * STRIDE + 3 + r);
            }
        }
        asm volatile("cp.async.commit_group;" ::: "memory");

        ull acc[8];
        acc[0] = acc[1] = acc[2] = acc[3] = pack2(b1a, b1a);
        acc[4] = acc[5] = acc[6] = acc[7] = pack2(b1b, b1b);

        // ---- layer 1 over 8 chunks, double-buffered ----
        for (int c = 0; c < NCH; c++) {
            if (c + 1 < NCH) {
                int k0n = (c + 1) * CH;
                unsigned wb = swc_u + (unsigned)((((c + 1) & 1) * CH * D_H) * 4);
                for (int i = tid; i < CH * D_H / 4; i += TPB)
                    cpa16(wb + (unsigned)(i * 16), We1 + k0n * D_H + i * 4);
                unsigned ib = sic_u + (unsigned)((((c + 1) & 1) * CH * ETT) * 4);
                const int* idxs = (k0n < 128) ? sfi : ssi;
                int goff = (k0n < 128) ? k0n : (k0n - 128);
                for (int idx = tid; idx < CH * ETT; idx += TPB) {
                    int r = idx >> 6, e = idx & 63;
                    cpa4(ib + (unsigned)(idx * 4), nf + idxs[e] * STRIDE + 3 + goff + r);
                }
                asm volatile("cp.async.commit_group;" ::: "memory");
                asm volatile("cp.async.wait_group 1;" ::: "memory");
            } else {
                asm volatile("cp.async.wait_group 0;" ::: "memory");
            }
            __syncthreads();   // chunk c visible

            const float* wrow = swc + (c & 1) * CH * D_H + j0;
            const float* xrow = sic + (c & 1) * CH * ETT + x8;
            #pragma unroll 4
            for (int r = 0; r < CH; r++) {
                step8(wrow, xrow, acc);
                wrow += D_H; xrow += ETT;
            }
            __syncthreads();   // done reading buffer before restage
        }
        // epilogue rows 256..272: dist2 + edge features
        {
            const float* wrow = sWe + j0;
            const float* xrow = sde + x8;
            #pragma unroll 4
            for (int r = 0; r < 17; r++) {
                step8(wrow, xrow, acc);
                wrow += D_H; xrow += ETT;
            }
        }

        // ---- silu + write m1 tile ----
        {
            float v0[8], v1[8];
            unpack2(acc[0], v0[0], v0[1]); unpack2(acc[1], v0[2], v0[3]);
            unpack2(acc[2], v0[4], v0[5]); unpack2(acc[3], v0[6], v0[7]);
            unpack2(acc[4], v1[0], v1[1]); unpack2(acc[5], v1[2], v1[3]);
            unpack2(acc[6], v1[4], v1[5]); unpack2(acc[7], v1[6], v1[7]);
            #pragma unroll
            for (int e = 0; e < 8; e++) { v0[e] = silu(v0[e]); v1[e] = silu(v1[e]); }
            float4* r0 = (float4*)(sm1 + (j0 + 0) * ETT + x8);
            r0[0] = make_float4(v0[0], v0[1], v0[2], v0[3]);
            r0[1] = make_float4(v0[4], v0[5], v0[6], v0[7]);
            float4* r1 = (float4*)(sm1 + (j0 + 1) * ETT + x8);
            r1[0] = make_float4(v1[0], v1[1], v1[2], v1[3]);
            r1[1] = make_float4(v1[4], v1[5], v1[6], v1[7]);
        }
        __syncthreads();

        // ---- layer 2 (W2 resident in smem) ----
        ull a2[8];
        a2[0] = a2[1] = a2[2] = a2[3] = pack2(b2a, b2a);
        a2[4] = a2[5] = a2[6] = a2[7] = pack2(b2b, b2b);
        {
            const float* wrow = sW2 + j0;
            const float* xrow = sm1 + x8;
            #pragma unroll 4
            for (int k = 0; k < D_H; k++) {
                step8(wrow, xrow, a2);
                wrow += D_H; xrow += ETT;
            }
        }
        float m0[8], m1v[8];
        unpack2(a2[0], m0[0], m0[1]); unpack2(a2[1], m0[2], m0[3]);
        unpack2(a2[2], m0[4], m0[5]); unpack2(a2[3], m0[6], m0[7]);
        unpack2(a2[4], m1v[0], m1v[1]); unpack2(a2[5], m1v[2], m1v[3]);
        unpack2(a2[6], m1v[4], m1v[5]); unpack2(a2[7], m1v[6], m1v[7]);
        #pragma unroll
        for (int e = 0; e < 8; e++) { m0[e] = silu(m0[e]); m1v[e] = silu(m1v[e]); }

        // ---- coord gate reduction over j ----
        {
            float cs[8];
            #pragma unroll
            for (int e = 0; e < 8; e++) cs[e] = m0[e] * wc0 + m1v[e] * wc1;
            #pragma unroll
            for (int off = 16; off > 0; off >>= 1) {
                #pragma unroll
                for (int e = 0; e < 8; e++) cs[e] += __shfl_xor_sync(0xffffffffu, cs[e], off);
            }
            if (lane == 0) {
                #pragma unroll
                for (int e = 0; e < 8; e++) scp[wid * 8 + e] = cs[e];
            }
        }
        __syncthreads();

        // ---- coord + count atomics ----
        if (tid < ETT && (e0 + tid) < E) {
            int s2 = tid >> 3, el = tid & 7;
            float c = bcv + scp[(2 * s2) * 8 + el] + scp[(2 * s2 + 1) * 8 + el];
            int fi = sfi[tid];
            atomicAdd(&g_csum[fi * 3 + 0], scd[0 * ETT + tid] * c);
            atomicAdd(&g_csum[fi * 3 + 1], scd[1 * ETT + tid] * c);
            atomicAdd(&g_csum[fi * 3 + 2], scd[2 * ETT + tid] * c);
            atomicAdd(&g_cnt[fi], 1.0f);
        }

        // ---- nbr_sum atomics ----
        #pragma unroll
        for (int e = 0; e < 8; e++) {
            int slot = x8 + e;
            if (e0 + slot < E) {
                int fi = sfi[slot];
                atomicAdd(&g_nbr[fi * D_H + j0], m0[e]);
                atomicAdd(&g_nbr[fi * D_H + j0 + 1], m1v[e]);
            }
        }
    }
}

// =====================================================================
// Node kernel: unchanged (16-node tiles, 256 threads)
// =====================================================================
__global__ void __launch_bounds__(256, 1) node_kernel(
    const float* __restrict__ nf,
    const float* __restrict__ Wn1, const float* __restrict__ bn1,
    const float* __restrict__ Wn2, const float* __restrict__ bn2,
    float* __restrict__ out, int N)
{
    extern __shared__ float sh[];
    float* sW1 = sh;                      // 256*128 = 32768
    float* sW2 = sW1 + 256 * D_H;         // 16384
    float* sin_ = sW2 + D_H * D_H;        // 256*16 = 4096
    float* st1 = sin_ + 256 * NTT;        // 128*16 = 2048

    const int tid = threadIdx.x;
    const int j = tid & 127;
    const int grp = tid >> 7;
    const int g8 = grp * 8;

    for (int i = tid; i < 256 * D_H; i += 256) sW1[i] = Wn1[i];
    for (int i = tid; i < D_H * D_H; i += 256) sW2[i] = Wn2[i];
    const float b1 = bn1[j];
    const float b2 = bn2[j];
    __syncthreads();

    const int ntiles = (N + NTT - 1) / NTT;

    for (int t = blockIdx.x; t < ntiles; t += gridDim.x) {
        const int n0 = t * NTT;
        __syncthreads();

        #pragma unroll
        for (int e = 0; e < 8; e++) {
            int s = g8 + e;
            int n = n0 + s; if (n >= N) n = N - 1;
            sin_[j * NTT + s] = nf[n * STRIDE + 3 + j];
            sin_[(D_H + j) * NTT + s] = g_nbr[n * D_H + j];
        }
        __syncthreads();

        ull a0 = pack2(b1, b1), a1 = a0, a2 = a0, a3 = a0;
        {
            const float* wcol = sW1 + j;
            const float* ib = sin_ + g8;
            #pragma unroll 4
            for (int k = 0; k < 256; k++) {
                float w = wcol[k * D_H];
                ull w2 = pack2(w, w);
                const ulonglong2* ip = (const ulonglong2*)(ib + k * NTT);
                ulonglong2 q = ip[0];
                a0 = fma2(q.x, w2, a0);
                a1 = fma2(q.y, w2, a1);
                ulonglong2 r = ip[1];
                a2 = fma2(r.x, w2, a2);
                a3 = fma2(r.y, w2, a3);
            }
        }
        {
            float v[8];
            unpack2(a0, v[0], v[1]); unpack2(a1, v[2], v[3]);
            unpack2(a2, v[4], v[5]); unpack2(a3, v[6], v[7]);
            #pragma unroll
            for (int e = 0; e < 8; e++) v[e] = silu(v[e]);
            float4* r4 = (float4*)(st1 + j * NTT + g8);
            r4[0] = make_float4(v[0], v[1], v[2], v[3]);
            r4[1] = make_float4(v[4], v[5], v[6], v[7]);
        }
        __syncthreads();

        ull c0 = pack2(b2, b2), c1 = c0, c2 = c0, c3 = c0;
        {
            const float* wcol = sW2 + j;
            const float* ib = st1 + g8;
            #pragma unroll 4
            for (int k = 0; k < D_H; k++) {
                float w = wcol[k * D_H];
                ull w2 = pack2(w, w);
                const ulonglong2* ip = (const ulonglong2*)(ib + k * NTT);
                ulonglong2 q = ip[0];
                c0 = fma2(q.x, w2, c0);
                c1 = fma2(q.y, w2, c1);
                ulonglong2 r = ip[1];
                c2 = fma2(r.x, w2, c2);
                c3 = fma2(r.y, w2, c3);
            }
        }
        float v[8];
        unpack2(c0, v[0], v[1]); unpack2(c1, v[2], v[3]);
        unpack2(c2, v[4], v[5]); unpack2(c3, v[6], v[7]);
        #pragma unroll
        for (int e = 0; e < 8; e++) {
            int n = n0 + g8 + e;
            if (n < N) out[n * STRIDE + 3 + j] = v[e];
        }

        if (tid < NTT) {
            int n = n0 + tid;
            if (n < N) {
                float cnt = fmaxf(g_cnt[n], 1.0f);
                float inv = 1.0f / cnt;
                out[n * STRIDE + 0] = nf[n * STRIDE + 0] + g_csum[n * 3 + 0] * inv;
                out[n * STRIDE + 1] = nf[n * STRIDE + 1] + g_csum[n * 3 + 1] * inv;
                out[n * STRIDE + 2] = nf[n * STRIDE + 2] + g_csum[n * 3 + 2] * inv;
            }
        }
    }
}

// =====================================================================
extern "C" void kernel_launch(void* const* d_in, const int* in_sizes, int n_in,
                              void* d_out, int out_size) {
    const float* nf  = (const float*)d_in[0];
    const int*   ei  = (const int*)d_in[1];
    const float* ef  = (const float*)d_in[2];
    const float* We1 = (const float*)d_in[3];
    const float* be1 = (const float*)d_in[4];
    const float* We2 = (const float*)d_in[5];
    const float* be2 = (const float*)d_in[6];
    const float* Wc  = (const float*)d_in[7];
    const float* bc  = (const float*)d_in[8];
    const float* Wn1 = (const float*)d_in[9];
    const float* bn1 = (const float*)d_in[10];
    const float* Wn2 = (const float*)d_in[11];
    const float* bn2 = (const float*)d_in[12];
    float* out = (float*)d_out;

    const int N = in_sizes[0] / STRIDE;
    const int E = in_sizes[2] / D_E;

    const int EDGE_SMEM = 40576 * 4;   // 162304 B
    const int NODE_SMEM = 55296 * 4;   // 221184 B
    cudaFuncSetAttribute(edge_kernel, cudaFuncAttributeMaxDynamicSharedMemorySize, EDGE_SMEM);
    cudaFuncSetAttribute(node_kernel, cudaFuncAttributeMaxDynamicSharedMemorySize, NODE_SMEM);

    zero_kernel<<<1024, 256>>>(N);
    edge_kernel<<<148, TPB, EDGE_SMEM>>>(nf, ei, ef, We1, be1, We2, be2, Wc, bc, N, E);
    node_kernel<<<148, 256, NODE_SMEM>>>(nf, Wn1, bn1, Wn2, bn2, out, N);
}

// round 8
// speedup vs baseline: 1.4778x; 1.0629x over previous
#include <cuda_runtime.h>

#define D_H 128
#define D_E 16
#define KE 273            // 2*128 + 1 + 16
#define STRIDE 131
#define ETT 96            // edges per block tile (edge kernel)
#define CH 32             // chunk rows, 256/32 = 8 chunks
#define NCH 8
#define TPB_E 768
#define NTT 64            // nodes per tile (node kernel)
#define TPB_N 512
#define MAXN 50000

// ---- scratch (device globals: no allocation allowed) ----
__device__ float g_nbr[MAXN * D_H];
__device__ float g_csum[MAXN * 3];
__device__ float g_cnt[MAXN];

typedef unsigned long long ull;

__device__ __forceinline__ ull pack2(float a, float b) {
    ull r; asm("mov.b64 %0, {%1, %2};" : "=l"(r) : "r"(__float_as_uint(a)), "r"(__float_as_uint(b)));
    return r;
}
__device__ __forceinline__ ull fma2(ull a, ull b, ull c) {
    ull d; asm("fma.rn.f32x2 %0, %1, %2, %3;" : "=l"(d) : "l"(a), "l"(b), "l"(c));
    return d;
}
__device__ __forceinline__ void unpack2(ull v, float& lo, float& hi) {
    unsigned l, h; asm("mov.b64 {%0, %1}, %2;" : "=r"(l), "=r"(h) : "l"(v));
    lo = __uint_as_float(l); hi = __uint_as_float(h);
}
__device__ __forceinline__ float silu(float x) { return x / (1.0f + __expf(-x)); }

__device__ __forceinline__ void cpa4(unsigned dst, const float* src) {
    asm volatile("cp.async.ca.shared.global [%0], [%1], 4;" :: "r"(dst), "l"(src));
}
__device__ __forceinline__ void cpa16(unsigned dst, const float* src) {
    asm volatile("cp.async.ca.shared.global [%0], [%1], 16;" :: "r"(dst), "l"(src));
}

// 8 FMA2 per k-step: 2 j's x 8 edges (4 f32x2 pairs)
__device__ __forceinline__ void step8(const float* __restrict__ w, const float* __restrict__ x, ull* a) {
    float2 wv = *(const float2*)w;
    ull w0 = pack2(wv.x, wv.x), w1 = pack2(wv.y, wv.y);
    ulonglong2 q = ((const ulonglong2*)x)[0];
    a[0] = fma2(q.x, w0, a[0]); a[4] = fma2(q.x, w1, a[4]);
    a[1] = fma2(q.y, w0, a[1]); a[5] = fma2(q.y, w1, a[5]);
    ulonglong2 r = ((const ulonglong2*)x)[1];
    a[2] = fma2(r.x, w0, a[2]); a[6] = fma2(r.x, w1, a[6]);
    a[3] = fma2(r.y, w0, a[3]); a[7] = fma2(r.y, w1, a[7]);
}

// ---- zero scratch each launch ----
__global__ void zero_kernel(int N) {
    int i = blockIdx.x * blockDim.x + threadIdx.x;
    int s = gridDim.x * blockDim.x;
    float4 z = make_float4(0.f, 0.f, 0.f, 0.f);
    float4* p = (float4*)g_nbr;
    int n4 = N * D_H / 4;
    for (int k = i; k < n4; k += s) p[k] = z;
    for (int k = i; k < N * 3; k += s) g_csum[k] = 0.f;
    for (int k = i; k < N; k += s) g_cnt[k] = 0.f;
}

// =====================================================================
// Edge kernel: 96-edge tiles, 768 threads = 12 edge-sets x 64 j-pairs
// (6 warps/SMSP). We1 streamed in 32-row chunks (weights + gathered
// inputs), double-buffered via cp.async. W2 + epilogue weights resident.
// =====================================================================
__global__ void __launch_bounds__(TPB_E, 1) edge_kernel(
    const float* __restrict__ nf, const int* __restrict__ ei, const float* __restrict__ ef,
    const float* __restrict__ We1, const float* __restrict__ be1,
    const float* __restrict__ We2, const float* __restrict__ be2,
    const float* __restrict__ Wc, const float* __restrict__ bc,
    int N, int E)
{
    extern __shared__ float sh[];
    float* sW2 = sh;                        // 16384
    float* sm1 = sW2 + D_H * D_H;           // 128*96 = 12288
    float* swc = sm1 + D_H * ETT;           // 2*32*128 = 8192
    float* sic = swc + 2 * CH * D_H;        // 2*32*96 = 6144
    float* sWe = sic + 2 * CH * ETT;        // 17*128 = 2176
    float* sde = sWe + 17 * D_H;            // 17*96 = 1632
    float* scd = sde + 17 * ETT;            // 3*96 = 288
    float* scp = scd + 3 * ETT;             // 24 warps * 8 = 192
    int* sfi = (int*)(scp + 192);           // 96
    int* ssi = sfi + ETT;                   // 96
    // total 47488 floats = 189952 B

    const int tid = threadIdx.x;
    const int lane = tid & 31, wid = tid >> 5;
    const int j6 = tid & 63;                // j-pair index
    const int s = tid >> 6;                 // edge set 0..11
    const int j0 = 2 * j6;
    const int x8 = 8 * s;

    // stage resident weights: W2 and We1 rows 256..272
    {
        const float4* b = (const float4*)We2; float4* d2 = (float4*)sW2;
        for (int i = tid; i < D_H * D_H / 4; i += TPB_E) d2[i] = b[i];
        const float4* e4 = (const float4*)(We1 + 256 * D_H); float4* d3 = (float4*)sWe;
        for (int i = tid; i < 17 * D_H / 4; i += TPB_E) d3[i] = e4[i];
    }
    const float b1a = be1[j0], b1b = be1[j0 + 1];
    const float b2a = be2[j0], b2b = be2[j0 + 1];
    const float wc0 = Wc[j0], wc1 = Wc[j0 + 1];
    const float bcv = bc[0];
    __syncthreads();

    const int* first = ei;
    const int* second = ei + E;
    const int ntiles = (E + ETT - 1) / ETT;
    const unsigned swc_u = (unsigned)__cvta_generic_to_shared(swc);
    const unsigned sic_u = (unsigned)__cvta_generic_to_shared(sic);

    for (int t = blockIdx.x; t < ntiles; t += gridDim.x) {
        const int e0 = t * ETT;
        __syncthreads();   // protect per-tile smem from prior-tile consumers

        // ---- stage A: indices, coord diffs, dist2, edge features ----
        if (tid < ETT) {
            int e = e0 + tid;
            int fi = 0, si = 0;
            if (e < E) { fi = first[e]; si = second[e]; }
            sfi[tid] = fi; ssi[tid] = si;
            float dx = nf[fi * STRIDE + 0] - nf[si * STRIDE + 0];
            float dy = nf[fi * STRIDE + 1] - nf[si * STRIDE + 1];
            float dz = nf[fi * STRIDE + 2] - nf[si * STRIDE + 2];
            scd[0 * ETT + tid] = dx; scd[1 * ETT + tid] = dy; scd[2 * ETT + tid] = dz;
            sde[tid] = dx * dx + dy * dy + dz * dz;
        }
        for (int idx = tid; idx < D_E * ETT; idx += TPB_E) {
            int f = idx / ETT, e = idx - f * ETT;
            int ee = e0 + e;
            sde[(1 + f) * ETT + e] = (ee < E) ? ef[ee * D_E + f] : 0.f;
        }
        __syncthreads();   // sfi/ssi visible before gathers

        // ---- stage chunk 0 (weights 16B + inputs 4B) ----
        {
            for (int i = tid; i < CH * D_H / 4; i += TPB_E)
                cpa16(swc_u + (unsigned)(i * 16), We1 + i * 4);
            for (int idx = tid; idx < CH * ETT; idx += TPB_E) {
                int r = idx / ETT, e = idx - r * ETT;
                cpa4(sic_u + (unsigned)(idx * 4), nf + sfi[e] * STRIDE + 3 + r);
            }
        }
        asm volatile("cp.async.commit_group;" ::: "memory");

        ull acc[8];
        acc[0] = acc[1] = acc[2] = acc[3] = pack2(b1a, b1a);
        acc[4] = acc[5] = acc[6] = acc[7] = pack2(b1b, b1b);

        // ---- layer 1 over 8 chunks, double-buffered ----
        for (int c = 0; c < NCH; c++) {
            if (c + 1 < NCH) {
                int k0n = (c + 1) * CH;
                unsigned wb = swc_u + (unsigned)((((c + 1) & 1) * CH * D_H) * 4);
                for (int i = tid; i < CH * D_H / 4; i += TPB_E)
                    cpa16(wb + (unsigned)(i * 16), We1 + k0n * D_H + i * 4);
                unsigned ib = sic_u + (unsigned)((((c + 1) & 1) * CH * ETT) * 4);
                const int* idxs = (k0n < 128) ? sfi : ssi;
                int goff = (k0n < 128) ? k0n : (k0n - 128);
                for (int idx = tid; idx < CH * ETT; idx += TPB_E) {
                    int r = idx / ETT, e = idx - r * ETT;
                    cpa4(ib + (unsigned)(idx * 4), nf + idxs[e] * STRIDE + 3 + goff + r);
                }
                asm volatile("cp.async.commit_group;" ::: "memory");
                asm volatile("cp.async.wait_group 1;" ::: "memory");
            } else {
                asm volatile("cp.async.wait_group 0;" ::: "memory");
            }
            __syncthreads();   // chunk c visible

            const float* wrow = swc + (c & 1) * CH * D_H + j0;
            const float* xrow = sic + (c & 1) * CH * ETT + x8;
            #pragma unroll 4
            for (int r = 0; r < CH; r++) {
                step8(wrow, xrow, acc);
                wrow += D_H; xrow += ETT;
            }
            __syncthreads();   // done reading buffer before restage
        }
        // epilogue rows 256..272: dist2 + edge features
        {
            const float* wrow = sWe + j0;
            const float* xrow = sde + x8;
            #pragma unroll 4
            for (int r = 0; r < 17; r++) {
                step8(wrow, xrow, acc);
                wrow += D_H; xrow += ETT;
            }
        }

        // ---- silu + write m1 tile ----
        {
            float v0[8], v1[8];
            unpack2(acc[0], v0[0], v0[1]); unpack2(acc[1], v0[2], v0[3]);
            unpack2(acc[2], v0[4], v0[5]); unpack2(acc[3], v0[6], v0[7]);
            unpack2(acc[4], v1[0], v1[1]); unpack2(acc[5], v1[2], v1[3]);
            unpack2(acc[6], v1[4], v1[5]); unpack2(acc[7], v1[6], v1[7]);
            #pragma unroll
            for (int e = 0; e < 8; e++) { v0[e] = silu(v0[e]); v1[e] = silu(v1[e]); }
            float4* r0 = (float4*)(sm1 + (j0 + 0) * ETT + x8);
            r0[0] = make_float4(v0[0], v0[1], v0[2], v0[3]);
            r0[1] = make_float4(v0[4], v0[5], v0[6], v0[7]);
            float4* r1 = (float4*)(sm1 + (j0 + 1) * ETT + x8);
            r1[0] = make_float4(v1[0], v1[1], v1[2], v1[3]);
            r1[1] = make_float4(v1[4], v1[5], v1[6], v1[7]);
        }
        __syncthreads();

        // ---- layer 2 (W2 resident in smem) ----
        ull a2[8];
        a2[0] = a2[1] = a2[2] = a2[3] = pack2(b2a, b2a);
        a2[4] = a2[5] = a2[6] = a2[7] = pack2(b2b, b2b);
        {
            const float* wrow = sW2 + j0;
            const float* xrow = sm1 + x8;
            #pragma unroll 4
            for (int k = 0; k < D_H; k++) {
                step8(wrow, xrow, a2);
                wrow += D_H; xrow += ETT;
            }
        }
        float m0[8], m1v[8];
        unpack2(a2[0], m0[0], m0[1]); unpack2(a2[1], m0[2], m0[3]);
        unpack2(a2[2], m0[4], m0[5]); unpack2(a2[3], m0[6], m0[7]);
        unpack2(a2[4], m1v[0], m1v[1]); unpack2(a2[5], m1v[2], m1v[3]);
        unpack2(a2[6], m1v[4], m1v[5]); unpack2(a2[7], m1v[6], m1v[7]);
        #pragma unroll
        for (int e = 0; e < 8; e++) { m0[e] = silu(m0[e]); m1v[e] = silu(m1v[e]); }

        // ---- coord gate reduction over j ----
        {
            float cs[8];
            #pragma unroll
            for (int e = 0; e < 8; e++) cs[e] = m0[e] * wc0 + m1v[e] * wc1;
            #pragma unroll
            for (int off = 16; off > 0; off >>= 1) {
                #pragma unroll
                for (int e = 0; e < 8; e++) cs[e] += __shfl_xor_sync(0xffffffffu, cs[e], off);
            }
            if (lane == 0) {
                #pragma unroll
                for (int e = 0; e < 8; e++) scp[wid * 8 + e] = cs[e];
            }
        }
        __syncthreads();

        // ---- coord + count atomics ----
        if (tid < ETT && (e0 + tid) < E) {
            int s2 = tid >> 3, el = tid & 7;
            float c = bcv + scp[(2 * s2) * 8 + el] + scp[(2 * s2 + 1) * 8 + el];
            int fi = sfi[tid];
            atomicAdd(&g_csum[fi * 3 + 0], scd[0 * ETT + tid] * c);
            atomicAdd(&g_csum[fi * 3 + 1], scd[1 * ETT + tid] * c);
            atomicAdd(&g_csum[fi * 3 + 2], scd[2 * ETT + tid] * c);
            atomicAdd(&g_cnt[fi], 1.0f);
        }

        // ---- nbr_sum atomics ----
        #pragma unroll
        for (int e = 0; e < 8; e++) {
            int slot = x8 + e;
            if (e0 + slot < E) {
                int fi = sfi[slot];
                atomicAdd(&g_nbr[fi * D_H + j0], m0[e]);
                atomicAdd(&g_nbr[fi * D_H + j0 + 1], m1v[e]);
            }
        }
    }
}

// =====================================================================
// Node kernel: 64-node tiles, 512 threads = 8 node-sets x 64 j-pairs.
// Wn1 streamed in 32-row chunks (contiguous inputs, no gather).
// W2n resident. 147KB smem -> 4 warps/SMSP.
// =====================================================================
__global__ void __launch_bounds__(TPB_N, 1) node_kernel(
    const float* __restrict__ nf,
    const float* __restrict__ Wn1, const float* __restrict__ bn1,
    const float* __restrict__ Wn2, const float* __restrict__ bn2,
    float* __restrict__ out, int N)
{
    extern __shared__ float sh[];
    float* sW2 = sh;                        // 16384
    float* st1 = sW2 + D_H * D_H;           // 128*64 = 8192
    float* swc = st1 + D_H * NTT;           // 2*32*128 = 8192
    float* sic = swc + 2 * CH * D_H;        // 2*32*64 = 4096
    // total 36864 floats = 147456 B

    const int tid = threadIdx.x;
    const int j6 = tid & 63;
    const int s = tid >> 6;                 // node set 0..7
    const int j0 = 2 * j6;
    const int x8 = 8 * s;

    {
        const float4* b = (const float4*)Wn2; float4* d2 = (float4*)sW2;
        for (int i = tid; i < D_H * D_H / 4; i += TPB_N) d2[i] = b[i];
    }
    const float b1a = bn1[j0], b1b = bn1[j0 + 1];
    const float b2a = bn2[j0], b2b = bn2[j0 + 1];
    __syncthreads();

    const int ntiles = (N + NTT - 1) / NTT;
    const unsigned swc_u = (unsigned)__cvta_generic_to_shared(swc);
    const unsigned sic_u = (unsigned)__cvta_generic_to_shared(sic);

    for (int t = blockIdx.x; t < ntiles; t += gridDim.x) {
        const int n0 = t * NTT;
        __syncthreads();   // prior-tile smem consumers done

        // ---- stage chunk 0: weights + h inputs ----
        for (int i = tid; i < CH * D_H / 4; i += TPB_N)
            cpa16(swc_u + (unsigned)(i * 16), Wn1 + i * 4);
        for (int idx = tid; idx < CH * NTT; idx += TPB_N) {
            int r = idx >> 6, e = idx & 63;
            int n = n0 + e; if (n >= N) n = N - 1;
            cpa4(sic_u + (unsigned)(idx * 4), nf + n * STRIDE + 3 + r);
        }
        asm volatile("cp.async.commit_group;" ::: "memory");

        ull acc[8];
        acc[0] = acc[1] = acc[2] = acc[3] = pack2(b1a, b1a);
        acc[4] = acc[5] = acc[6] = acc[7] = pack2(b1b, b1b);

        // ---- layer 1 over 8 chunks (rows 0..255), double-buffered ----
        for (int c = 0; c < NCH; c++) {
            if (c + 1 < NCH) {
                int k0n = (c + 1) * CH;
                unsigned wb = swc_u + (unsigned)((((c + 1) & 1) * CH * D_H) * 4);
                for (int i = tid; i < CH * D_H / 4; i += TPB_N)
                    cpa16(wb + (unsigned)(i * 16), Wn1 + k0n * D_H + i * 4);
                unsigned ib = sic_u + (unsigned)((((c + 1) & 1) * CH * NTT) * 4);
                const float* base = (k0n < 128) ? (nf + 3 + k0n) : (g_nbr + (k0n - 128));
                const int rs = (k0n < 128) ? STRIDE : D_H;
                for (int idx = tid; idx < CH * NTT; idx += TPB_N) {
                    int r = idx >> 6, e = idx & 63;
                    int n = n0 + e; if (n >= N) n = N - 1;
                    cpa4(ib + (unsigned)(idx * 4), base + n * rs + r);
                }
                asm volatile("cp.async.commit_group;" ::: "memory");
                asm volatile("cp.async.wait_group 1;" ::: "memory");
            } else {
                asm volatile("cp.async.wait_group 0;" ::: "memory");
            }
            __syncthreads();

            const float* wrow = swc + (c & 1) * CH * D_H + j0;
            const float* xrow = sic + (c & 1) * CH * NTT + x8;
            #pragma unroll 4
            for (int r = 0; r < CH; r++) {
                step8(wrow, xrow, acc);
                wrow += D_H; xrow += NTT;
            }
            __syncthreads();
        }

        // ---- silu + write t1 tile ----
        {
            float v0[8], v1[8];
            unpack2(acc[0], v0[0], v0[1]); unpack2(acc[1], v0[2], v0[3]);
            unpack2(acc[2], v0[4], v0[5]); unpack2(acc[3], v0[6], v0[7]);
            unpack2(acc[4], v1[0], v1[1]); unpack2(acc[5], v1[2], v1[3]);
            unpack2(acc[6], v1[4], v1[5]); unpack2(acc[7], v1[6], v1[7]);
            #pragma unroll
            for (int e = 0; e < 8; e++) { v0[e] = silu(v0[e]); v1[e] = silu(v1[e]); }
            float4* r0 = (float4*)(st1 + (j0 + 0) * NTT + x8);
            r0[0] = make_float4(v0[0], v0[1], v0[2], v0[3]);
            r0[1] = make_float4(v0[4], v0[5], v0[6], v0[7]);
            float4* r1 = (float4*)(st1 + (j0 + 1) * NTT + x8);
            r1[0] = make_float4(v1[0], v1[1], v1[2], v1[3]);
            r1[1] = make_float4(v1[4], v1[5], v1[6], v1[7]);
        }
        __syncthreads();

        // ---- layer 2 (resident) ----
        ull a2[8];
        a2[0] = a2[1] = a2[2] = a2[3] = pack2(b2a, b2a);
        a2[4] = a2[5] = a2[6] = a2[7] = pack2(b2b, b2b);
        {
            const float* wrow = sW2 + j0;
            const float* xrow = st1 + x8;
            #pragma unroll 4
            for (int k = 0; k < D_H; k++) {
                step8(wrow, xrow, a2);
                wrow += D_H; xrow += NTT;
            }
        }
        float v0[8], v1[8];
        unpack2(a2[0], v0[0], v0[1]); unpack2(a2[1], v0[2], v0[3]);
        unpack2(a2[2], v0[4], v0[5]); unpack2(a2[3], v0[6], v0[7]);
        unpack2(a2[4], v1[0], v1[1]); unpack2(a2[5], v1[2], v1[3]);
        unpack2(a2[6], v1[4], v1[5]); unpack2(a2[7], v1[6], v1[7]);
        #pragma unroll
        for (int e = 0; e < 8; e++) {
            int n = n0 + x8 + e;
            if (n < N) {
                out[n * STRIDE + 3 + j0] = v0[e];
                out[n * STRIDE + 3 + j0 + 1] = v1[e];
            }
        }

        // ---- coords output ----
        if (tid < NTT) {
            int n = n0 + tid;
            if (n < N) {
                float cnt = fmaxf(g_cnt[n], 1.0f);
                float inv = 1.0f / cnt;
                out[n * STRIDE + 0] = nf[n * STRIDE + 0] + g_csum[n * 3 + 0] * inv;
                out[n * STRIDE + 1] = nf[n * STRIDE + 1] + g_csum[n * 3 + 1] * inv;
                out[n * STRIDE + 2] = nf[n * STRIDE + 2] + g_csum[n * 3 + 2] * inv;
            }
        }
    }
}

// =====================================================================
extern "C" void kernel_launch(void* const* d_in, const int* in_sizes, int n_in,
                              void* d_out, int out_size) {
    const float* nf  = (const float*)d_in[0];
    const int*   ei  = (const int*)d_in[1];
    const float* ef  = (const float*)d_in[2];
    const float* We1 = (const float*)d_in[3];
    const float* be1 = (const float*)d_in[4];
    const float* We2 = (const float*)d_in[5];
    const float* be2 = (const float*)d_in[6];
    const float* Wc  = (const float*)d_in[7];
    const float* bc  = (const float*)d_in[8];
    const float* Wn1 = (const float*)d_in[9];
    const float* bn1 = (const float*)d_in[10];
    const float* Wn2 = (const float*)d_in[11];
    const float* bn2 = (const float*)d_in[12];
    float* out = (float*)d_out;

    const int N = in_sizes[0] / STRIDE;
    const int E = in_sizes[2] / D_E;

    const int EDGE_SMEM = 47488 * 4;   // 189952 B
    const int NODE_SMEM = 36864 * 4;   // 147456 B
    cudaFuncSetAttribute(edge_kernel, cudaFuncAttributeMaxDynamicSharedMemorySize, EDGE_SMEM);
    cudaFuncSetAttribute(node_kernel, cudaFuncAttributeMaxDynamicSharedMemorySize, NODE_SMEM);

    zero_kernel<<<1024, 256>>>(N);
    edge_kernel<<<148, TPB_E, EDGE_SMEM>>>(nf, ei, ef, We1, be1, We2, be2, Wc, bc, N, E);
    node_kernel<<<148, TPB_N, NODE_SMEM>>>(nf, Wn1, bn1, Wn2, bn2, out, N);
}

// round 11
// speedup vs baseline: 2.6120x; 1.7675x over previous
#include <cuda_runtime.h>
#include <cuda_bf16.h>
#include <cstdint>

#define D_H 128
#define STRIDE 131
#define MAXN 50000
#define MAXE 800000
#define NTT 64
#define TPB_N 512
#define CH 32
#define NCH 8

// smem offsets (bytes), all 16-aligned
#define X1H_OFF 0u
#define X1L_OFF 37888u
#define WB_OFF  75776u      // [buf][split][128*40*2=10240]; buf stride 20480
#define X2H_OFF 116736u
#define X2L_OFF 134144u
#define W2H_OFF 151552u
#define W2L_OFF 186368u
#define SFI_OFF 221184u     // int[2][64]
#define SCD_OFF 221696u     // float[2][192]
#define SCP_OFF 223232u     // float[8][64]
#define EDGE_SMEM 225280

__device__ float g_nbr[MAXN * D_H];
__device__ float g_csum[MAXN * 3];
__device__ float g_cnt[MAXN];
__device__ uint16_t g_h_hi[MAXN * 128];
__device__ uint16_t g_h_lo[MAXN * 128];
__device__ uint16_t g_ef_hi[MAXE * 16];
__device__ uint16_t g_ef_lo[MAXE * 16];
__device__ uint16_t g_W1Th[128 * 288];
__device__ uint16_t g_W1Tl[128 * 288];

typedef unsigned long long ull;

__device__ __forceinline__ uint32_t smem_u32(const void* p) {
    uint32_t a;
    asm("{ .reg .u64 t; cvta.to.shared.u64 t, %1; cvt.u32.u64 %0, t; }" : "=r"(a) : "l"(p));
    return a;
}
__device__ __forceinline__ float silu(float x) { return x / (1.0f + __expf(-x)); }
__device__ __forceinline__ void cpa16(uint32_t dst, const void* src) {
    asm volatile("cp.async.ca.shared.global [%0], [%1], 16;" :: "r"(dst), "l"(src));
}
__device__ __forceinline__ void cpa4(uint32_t dst, const void* src) {
    asm volatile("cp.async.ca.shared.global [%0], [%1], 4;" :: "r"(dst), "l"(src));
}
#define CPA_COMMIT() asm volatile("cp.async.commit_group;" ::: "memory")
#define CPA_WAIT0()  asm volatile("cp.async.wait_group 0;" ::: "memory")
__device__ __forceinline__ void sts16(uint32_t a, uint16_t v) { asm volatile("st.shared.u16 [%0], %1;" :: "r"(a), "h"(v)); }
__device__ __forceinline__ void split_bf16(float v, uint16_t& hi, uint16_t& lo) {
    __nv_bfloat16 h = __float2bfloat16(v);
    __nv_bfloat16 l = __float2bfloat16(v - __bfloat162float(h));
    hi = __bfloat16_as_ushort(h); lo = __bfloat16_as_ushort(l);
}
__device__ __forceinline__ void ldsm4(uint32_t a, uint32_t* r) {
    asm volatile("ldmatrix.sync.aligned.m8n8.x4.shared.b16 {%0,%1,%2,%3}, [%4];"
        : "=r"(r[0]), "=r"(r[1]), "=r"(r[2]), "=r"(r[3]) : "r"(a));
}
__device__ __forceinline__ void ldsm2(uint32_t a, uint32_t* r) {
    asm volatile("ldmatrix.sync.aligned.m8n8.x2.shared.b16 {%0,%1}, [%2];"
        : "=r"(r[0]), "=r"(r[1]) : "r"(a));
}
__device__ __forceinline__ void mma_bf16(float* d, const uint32_t* a, const uint32_t* b) {
    asm volatile("mma.sync.aligned.m16n8k16.row.col.f32.bf16.bf16.f32 "
        "{%0,%1,%2,%3}, {%4,%5,%6,%7}, {%8,%9}, {%0,%1,%2,%3};"
        : "+f"(d[0]), "+f"(d[1]), "+f"(d[2]), "+f"(d[3])
        : "r"(a[0]), "r"(a[1]), "r"(a[2]), "r"(a[3]), "r"(b[0]), "r"(b[1]));
}

// ---------------- prep kernels ----------------
__global__ void zero_kernel(int N) {
    int i = blockIdx.x * blockDim.x + threadIdx.x, s = gridDim.x * blockDim.x;
    float4 z = make_float4(0.f, 0.f, 0.f, 0.f);
    float4* p = (float4*)g_nbr; int n4 = N * D_H / 4;
    for (int k = i; k < n4; k += s) p[k] = z;
    for (int k = i; k < N * 3; k += s) g_csum[k] = 0.f;
    for (int k = i; k < N; k += s) g_cnt[k] = 0.f;
}
__global__ void prep_h(const float* __restrict__ nf, int N) {
    int i = blockIdx.x * blockDim.x + threadIdx.x, s = gridDim.x * blockDim.x;
    for (int idx = i; idx < N * 128; idx += s) {
        int n = idx >> 7, j = idx & 127;
        uint16_t h, l; split_bf16(nf[n * STRIDE + 3 + j], h, l);
        g_h_hi[idx] = h; g_h_lo[idx] = l;
    }
}
__global__ void prep_ef(const float* __restrict__ ef, int E) {
    int i = blockIdx.x * blockDim.x + threadIdx.x, s = gridDim.x * blockDim.x;
    for (int idx = i; idx < E * 16; idx += s) {
        uint16_t h, l; split_bf16(ef[idx], h, l);
        g_ef_hi[idx] = h; g_ef_lo[idx] = l;
    }
}
// W1T[j][k]: k 0-255 = h rows, 256-271 = ef rows (We1 257..272), 272 = dist2 row (We1 256), 273+ = 0
__global__ void prep_w1(const float* __restrict__ We1) {
    int idx = blockIdx.x * blockDim.x + threadIdx.x;
    if (idx >= 128 * 288) return;
    int j = idx / 288, k = idx % 288;
    float v = 0.f;
    if (k < 256) v = We1[k * 128 + j];
    else if (k < 272) v = We1[(257 + (k - 256)) * 128 + j];
    else if (k == 272) v = We1[256 * 128 + j];
    uint16_t h, l; split_bf16(v, h, l);
    g_W1Th[idx] = h; g_W1Tl[idx] = l;
}

// ---------------- edge kernel (warp mma, bf16 split) ----------------
__device__ __forceinline__ void stage_x1(uint32_t sb, char* smem, int t, int nb,
    const float* __restrict__ nf, const int* __restrict__ first, const int* __restrict__ second, int E)
{
    const int tid = threadIdx.x;
    if (tid < 64) {
        int e = tid, eg = min(t * 64 + e, E - 1);
        int fi = first[eg], si = second[eg];
        ((int*)(smem + SFI_OFF))[nb * 64 + e] = fi;
        float dx = nf[fi * STRIDE] - nf[si * STRIDE];
        float dy = nf[fi * STRIDE + 1] - nf[si * STRIDE + 1];
        float dz = nf[fi * STRIDE + 2] - nf[si * STRIDE + 2];
        float* sc = (float*)(smem + SCD_OFF) + nb * 192;
        sc[e] = dx; sc[64 + e] = dy; sc[128 + e] = dz;
        uint16_t h, l; split_bf16(dx * dx + dy * dy + dz * dz, h, l);
        sts16(sb + X1H_OFF + (uint32_t)((e * 296 + 272) * 2), h);
        sts16(sb + X1L_OFF + (uint32_t)((e * 296 + 272) * 2), l);
    }
    {   // ef -> cols 256..271
        int e = tid & 63, g = (tid >> 6) & 1, mat = tid >> 7;
        int eg = min(t * 64 + e, E - 1);
        const uint16_t* src = (mat ? g_ef_lo : g_ef_hi) + eg * 16 + g * 8;
        cpa16(sb + (mat ? X1L_OFF : X1H_OFF) + (uint32_t)((e * 296 + 256 + g * 8) * 2), src);
    }
    #pragma unroll
    for (int i = 0; i < 16; i++) {   // h -> cols 0..255 (first 0-127, second 128-255)
        int idx = tid + i * 256;
        int g = idx & 31, e = (idx >> 5) & 63, mat = idx >> 11;
        int eg = min(t * 64 + e, E - 1);
        int node = (g < 16) ? first[eg] : second[eg];
        const uint16_t* src = (mat ? g_h_lo : g_h_hi) + node * 128 + (g & 15) * 8;
        cpa16(sb + (mat ? X1L_OFF : X1H_OFF) + (uint32_t)((e * 296 + g * 8) * 2), src);
    }
}
__device__ __forceinline__ void stage_w1(uint32_t sb, int c, int wb) {
    const int tid = threadIdx.x;
    #pragma unroll
    for (int i = 0; i < 4; i++) {
        int idx = tid + i * 256;
        int g = idx & 3, j = (idx >> 2) & 127, mat = idx >> 9;
        const uint16_t* src = (mat ? g_W1Tl : g_W1Th) + j * 288 + c * 32 + g * 8;
        cpa16(sb + WB_OFF + (uint32_t)(wb * 20480 + mat * 10240 + (j * 40 + g * 8) * 2), src);
    }
}

__global__ void __launch_bounds__(256, 1) edge_kernel(
    const float* __restrict__ nf, const int* __restrict__ ei,
    const float* __restrict__ be1, const float* __restrict__ We2, const float* __restrict__ be2,
    const float* __restrict__ Wc, const float* __restrict__ bc, int N, int E)
{
    extern __shared__ char smem[];
    const uint32_t sb = smem_u32(smem);
    const int tid = threadIdx.x, w = tid >> 5, lane = tid & 31;
    const int* first = ei;
    const int* second = ei + E;
    int* sfi = (int*)(smem + SFI_OFF);
    float* scp = (float*)(smem + SCP_OFF);

    // one-time: zero X1 pad cols 273..287; convert W2 -> smem bf16 split [j][136]
    for (int idx = tid; idx < 64 * 15; idx += 256) {
        int e = idx / 15, c = 273 + idx % 15;
        sts16(sb + X1H_OFF + (uint32_t)((e * 296 + c) * 2), 0);
        sts16(sb + X1L_OFF + (uint32_t)((e * 296 + c) * 2), 0);
    }
    for (int idx = tid; idx < 128 * 128; idx += 256) {
        int k = idx >> 7, j = idx & 127;
        uint16_t h, l; split_bf16(We2[k * 128 + j], h, l);
        sts16(sb + W2H_OFF + (uint32_t)((j * 136 + k) * 2), h);
        sts16(sb + W2L_OFF + (uint32_t)((j * 136 + k) * 2), l);
    }

    const int j1 = 16 * w + (lane >> 2), j2 = j1 + 8;
    const float b1a = be1[j1], b1b = be1[j2];
    const float b2a = be2[j1], b2b = be2[j2];
    const float wc1 = Wc[j1], wc2 = Wc[j2];
    const float bcv = bc[0];

    // ldmatrix lane offsets
    const int r_a = (lane & 7) + ((lane >> 3) & 1) * 8;
    const int kk_a = ((lane >> 4) & 1) * 8;
    const uint32_t aoff1 = (uint32_t)(((16 * w + r_a) * 40 + kk_a) * 2);
    const uint32_t aoff2 = (uint32_t)(((16 * w + r_a) * 136 + kk_a) * 2);
    const uint32_t boff1 = (uint32_t)(((lane & 7) * 296 + ((lane >> 3) & 1) * 8) * 2);
    const uint32_t boff2 = (uint32_t)(((lane & 7) * 136 + ((lane >> 3) & 1) * 8) * 2);

    const int ntiles = (E + 63) / 64;
    int buf = 0;
    __syncthreads();
    if ((int)blockIdx.x < ntiles) {
        stage_x1(sb, smem, blockIdx.x, 0, nf, first, second, E);
        stage_w1(sb, 0, 0);
        CPA_COMMIT();
    }

    for (int t = blockIdx.x; t < ntiles; t += gridDim.x, buf ^= 1) {
        CPA_WAIT0();
        __syncthreads();

        float acc[8][4];
        #pragma unroll
        for (int n = 0; n < 8; n++) { acc[n][0] = b1a; acc[n][1] = b1a; acc[n][2] = b1b; acc[n][3] = b1b; }

        // ---- layer 1: 9 chunks x 2 k-steps, W double-buffered ----
        for (int c = 0; c < 9; c++) {
            if (c < 8) {
                stage_w1(sb, c + 1, (c + 1) & 1);
                CPA_COMMIT();
                asm volatile("cp.async.wait_group 1;" ::: "memory");
            } else CPA_WAIT0();
            __syncthreads();
            #pragma unroll
            for (int s = 0; s < 2; s++) {
                uint32_t ah[4], al[4];
                uint32_t aB = sb + WB_OFF + (uint32_t)((c & 1) * 20480) + aoff1 + (uint32_t)(s * 32);
                ldsm4(aB, ah);
                ldsm4(aB + 10240u, al);
                uint32_t bB = sb + X1H_OFF + boff1 + (uint32_t)((c * 32 + s * 16) * 2);
                #pragma unroll
                for (int n = 0; n < 8; n++) {
                    uint32_t bh[2], bl[2];
                    ldsm2(bB + (uint32_t)(n * 4736), bh);
                    ldsm2(bB + (X1L_OFF - X1H_OFF) + (uint32_t)(n * 4736), bl);
                    mma_bf16(acc[n], ah, bh);
                    mma_bf16(acc[n], ah, bl);
                    mma_bf16(acc[n], al, bh);
                }
            }
            __syncthreads();
        }

        // prefetch next tile X1 + W chunk0 (overlaps epilogues + layer 2)
        int tn = t + gridDim.x;
        if (tn < ntiles) {
            stage_x1(sb, smem, tn, buf ^ 1, nf, first, second, E);
            stage_w1(sb, 0, 0);
            CPA_COMMIT();
        }

        // ---- epi1: silu -> X2 (bf16 split, [e][j] stride 136) ----
        #pragma unroll
        for (int n = 0; n < 8; n++) {
            int e0 = 8 * n + 2 * (lane & 3);
            float v[4] = { silu(acc[n][0]), silu(acc[n][1]), silu(acc[n][2]), silu(acc[n][3]) };
            const int ee[4] = { e0, e0 + 1, e0, e0 + 1 };
            const int jj[4] = { j1, j1, j2, j2 };
            #pragma unroll
            for (int q = 0; q < 4; q++) {
                uint16_t h, l; split_bf16(v[q], h, l);
                uint32_t o = (uint32_t)((ee[q] * 136 + jj[q]) * 2);
                sts16(sb + X2H_OFF + o, h);
                sts16(sb + X2L_OFF + o, l);
            }
        }
        __syncthreads();

        // ---- layer 2: 8 k-steps, W2/X2 resident ----
        float a2[8][4];
        #pragma unroll
        for (int n = 0; n < 8; n++) { a2[n][0] = b2a; a2[n][1] = b2a; a2[n][2] = b2b; a2[n][3] = b2b; }
        #pragma unroll
        for (int ks = 0; ks < 8; ks++) {
            uint32_t ah[4], al[4];
            ldsm4(sb + W2H_OFF + aoff2 + (uint32_t)(ks * 32), ah);
            ldsm4(sb + W2L_OFF + aoff2 + (uint32_t)(ks * 32), al);
            uint32_t bB = sb + X2H_OFF + boff2 + (uint32_t)(ks * 32);
            #pragma unroll
            for (int n = 0; n < 8; n++) {
                uint32_t bh[2], bl[2];
                ldsm2(bB + (uint32_t)(n * 2176), bh);
                ldsm2(bB + (X2L_OFF - X2H_OFF) + (uint32_t)(n * 2176), bl);
                mma_bf16(a2[n], ah, bh);
                mma_bf16(a2[n], ah, bl);
                mma_bf16(a2[n], al, bh);
            }
        }

        // ---- epi2: silu -> atomics + coord gate ----
        #pragma unroll
        for (int n = 0; n < 8; n++) {
            int e0 = 8 * n + 2 * (lane & 3);
            float m0 = silu(a2[n][0]), m1 = silu(a2[n][1]), m2 = silu(a2[n][2]), m3 = silu(a2[n][3]);
            int ge0 = t * 64 + e0;
            if (ge0 < E) {
                int f0 = sfi[buf * 64 + e0];
                atomicAdd(&g_nbr[f0 * 128 + j1], m0);
                atomicAdd(&g_nbr[f0 * 128 + j2], m2);
            }
            if (ge0 + 1 < E) {
                int f1 = sfi[buf * 64 + e0 + 1];
                atomicAdd(&g_nbr[f1 * 128 + j1], m1);
                atomicAdd(&g_nbr[f1 * 128 + j2], m3);
            }
            float p0 = m0 * wc1 + m2 * wc2, p1 = m1 * wc1 + m3 * wc2;
            p0 += __shfl_xor_sync(~0u, p0, 4);  p1 += __shfl_xor_sync(~0u, p1, 4);
            p0 += __shfl_xor_sync(~0u, p0, 8);  p1 += __shfl_xor_sync(~0u, p1, 8);
            p0 += __shfl_xor_sync(~0u, p0, 16); p1 += __shfl_xor_sync(~0u, p1, 16);
            if ((lane >> 2) == 0) { scp[w * 64 + e0] = p0; scp[w * 64 + e0 + 1] = p1; }
        }
        __syncthreads();
        if (tid < 64 && t * 64 + tid < E) {
            int e = tid, fi = sfi[buf * 64 + e];
            float c = bcv;
            #pragma unroll
            for (int k2 = 0; k2 < 8; k2++) c += scp[k2 * 64 + e];
            float* sc = (float*)(smem + SCD_OFF) + buf * 192;
            atomicAdd(&g_csum[fi * 3 + 0], sc[e] * c);
            atomicAdd(&g_csum[fi * 3 + 1], sc[64 + e] * c);
            atomicAdd(&g_csum[fi * 3 + 2], sc[128 + e] * c);
            atomicAdd(&g_cnt[fi], 1.0f);
        }
        __syncthreads();
    }
}

// ---------------- node kernel (unchanged R8, passing) ----------------
__device__ __forceinline__ ull pk2(float a, float b) {
    ull r; asm("mov.b64 %0, {%1, %2};" : "=l"(r) : "r"(__float_as_uint(a)), "r"(__float_as_uint(b))); return r;
}
__device__ __forceinline__ ull fm2(ull a, ull b, ull c) {
    ull d; asm("fma.rn.f32x2 %0, %1, %2, %3;" : "=l"(d) : "l"(a), "l"(b), "l"(c)); return d;
}
__device__ __forceinline__ void up2(ull v, float& lo, float& hi) {
    unsigned l, h; asm("mov.b64 {%0, %1}, %2;" : "=r"(l), "=r"(h) : "l"(v));
    lo = __uint_as_float(l); hi = __uint_as_float(h);
}
__device__ __forceinline__ void nstep8(const float* __restrict__ w, const float* __restrict__ x, ull* a) {
    float2 wv = *(const float2*)w;
    ull w0 = pk2(wv.x, wv.x), w1 = pk2(wv.y, wv.y);
    ulonglong2 q = ((const ulonglong2*)x)[0];
    a[0] = fm2(q.x, w0, a[0]); a[4] = fm2(q.x, w1, a[4]);
    a[1] = fm2(q.y, w0, a[1]); a[5] = fm2(q.y, w1, a[5]);
    ulonglong2 r = ((const ulonglong2*)x)[1];
    a[2] = fm2(r.x, w0, a[2]); a[6] = fm2(r.x, w1, a[6]);
    a[3] = fm2(r.y, w0, a[3]); a[7] = fm2(r.y, w1, a[7]);
}
__global__ void __launch_bounds__(TPB_N, 1) node_kernel(
    const float* __restrict__ nf,
    const float* __restrict__ Wn1, const float* __restrict__ bn1,
    const float* __restrict__ Wn2, const float* __restrict__ bn2,
    float* __restrict__ out, int N)
{
    extern __shared__ float sh[];
    float* sW2 = sh;
    float* st1 = sW2 + D_H * D_H;
    float* swc = st1 + D_H * NTT;
    float* sic = swc + 2 * CH * D_H;
    const int tid = threadIdx.x;
    const int j0 = 2 * (tid & 63);
    const int x8 = 8 * (tid >> 6);
    { const float4* b = (const float4*)Wn2; float4* d2 = (float4*)sW2;
      for (int i = tid; i < D_H * D_H / 4; i += TPB_N) d2[i] = b[i]; }
    const float b1a = bn1[j0], b1b = bn1[j0 + 1], b2a = bn2[j0], b2b = bn2[j0 + 1];
    __syncthreads();
    const int ntiles = (N + NTT - 1) / NTT;
    const unsigned swc_u = (unsigned)__cvta_generic_to_shared(swc);
    const unsigned sic_u = (unsigned)__cvta_generic_to_shared(sic);
    for (int t = blockIdx.x; t < ntiles; t += gridDim.x) {
        const int n0 = t * NTT;
        __syncthreads();
        for (int i = tid; i < CH * D_H / 4; i += TPB_N) cpa16(swc_u + (unsigned)(i * 16), Wn1 + i * 4);
        for (int idx = tid; idx < CH * NTT; idx += TPB_N) {
            int r = idx >> 6, e = idx & 63, n = min(n0 + e, N - 1);
            cpa4(sic_u + (unsigned)(idx * 4), nf + n * STRIDE + 3 + r);
        }
        CPA_COMMIT();
        ull acc[8];
        acc[0] = acc[1] = acc[2] = acc[3] = pk2(b1a, b1a);
        acc[4] = acc[5] = acc[6] = acc[7] = pk2(b1b, b1b);
        for (int c = 0; c < NCH; c++) {
            if (c + 1 < NCH) {
                int k0n = (c + 1) * CH;
                unsigned wb = swc_u + (unsigned)((((c + 1) & 1) * CH * D_H) * 4);
                for (int i = tid; i < CH * D_H / 4; i += TPB_N) cpa16(wb + (unsigned)(i * 16), Wn1 + k0n * D_H + i * 4);
                unsigned ib = sic_u + (unsigned)((((c + 1) & 1) * CH * NTT) * 4);
                const float* base = (k0n < 128) ? (nf + 3 + k0n) : (g_nbr + (k0n - 128));
                const int rs = (k0n < 128) ? STRIDE : D_H;
                for (int idx = tid; idx < CH * NTT; idx += TPB_N) {
                    int r = idx >> 6, e = idx & 63, n = min(n0 + e, N - 1);
                    cpa4(ib + (unsigned)(idx * 4), base + n * rs + r);
                }
                CPA_COMMIT();
                asm volatile("cp.async.wait_group 1;" ::: "memory");
            } else CPA_WAIT0();
            __syncthreads();
            const float* wrow = swc + (c & 1) * CH * D_H + j0;
            const float* xrow = sic + (c & 1) * CH * NTT + x8;
            #pragma unroll 4
            for (int r = 0; r < CH; r++) { nstep8(wrow, xrow, acc); wrow += D_H; xrow += NTT; }
            __syncthreads();
        }
        {
            float v0[8], v1[8];
            up2(acc[0], v0[0], v0[1]); up2(acc[1], v0[2], v0[3]); up2(acc[2], v0[4], v0[5]); up2(acc[3], v0[6], v0[7]);
            up2(acc[4], v1[0], v1[1]); up2(acc[5], v1[2], v1[3]); up2(acc[6], v1[4], v1[5]); up2(acc[7], v1[6], v1[7]);
            #pragma unroll
            for (int e = 0; e < 8; e++) { v0[e] = silu(v0[e]); v1[e] = silu(v1[e]); }
            float4* r0 = (float4*)(st1 + (j0 + 0) * NTT + x8);
            r0[0] = make_float4(v0[0], v0[1], v0[2], v0[3]); r0[1] = make_float4(v0[4], v0[5], v0[6], v0[7]);
            float4* r1 = (float4*)(st1 + (j0 + 1) * NTT + x8);
            r1[0] = make_float4(v1[0], v1[1], v1[2], v1[3]); r1[1] = make_float4(v1[4], v1[5], v1[6], v1[7]);
        }
        __syncthreads();
        ull a2[8];
        a2[0] = a2[1] = a2[2] = a2[3] = pk2(b2a, b2a);
        a2[4] = a2[5] = a2[6] = a2[7] = pk2(b2b, b2b);
        { const float* wrow = sW2 + j0; const float* xrow = st1 + x8;
          #pragma unroll 4
          for (int k = 0; k < D_H; k++) { nstep8(wrow, xrow, a2); wrow += D_H; xrow += NTT; } }
        float v0[8], v1[8];
        up2(a2[0], v0[0], v0[1]); up2(a2[1], v0[2], v0[3]); up2(a2[2], v0[4], v0[5]); up2(a2[3], v0[6], v0[7]);
        up2(a2[4], v1[0], v1[1]); up2(a2[5], v1[2], v1[3]); up2(a2[6], v1[4], v1[5]); up2(a2[7], v1[6], v1[7]);
        #pragma unroll
        for (int e = 0; e < 8; e++) {
            int n = n0 + x8 + e;
            if (n < N) { out[n * STRIDE + 3 + j0] = v0[e]; out[n * STRIDE + 3 + j0 + 1] = v1[e]; }
        }
        if (tid < NTT) {
            int n = n0 + tid;
            if (n < N) {
                float inv = 1.0f / fmaxf(g_cnt[n], 1.0f);
                out[n * STRIDE + 0] = nf[n * STRIDE + 0] + g_csum[n * 3 + 0] * inv;
                out[n * STRIDE + 1] = nf[n * STRIDE + 1] + g_csum[n * 3 + 1] * inv;
                out[n * STRIDE + 2] = nf[n * STRIDE + 2] + g_csum[n * 3 + 2] * inv;
            }
        }
    }
}

extern "C" void kernel_launch(void* const* d_in, const int* in_sizes, int n_in,
                              void* d_out, int out_size) {
    const float* nf  = (const float*)d_in[0];
    const int*   ei  = (const int*)d_in[1];
    const float* ef  = (const float*)d_in[2];
    const float* We1 = (const float*)d_in[3];
    const float* be1 = (const float*)d_in[4];
    const float* We2 = (const float*)d_in[5];
    const float* be2 = (const float*)d_in[6];
    const float* Wc  = (const float*)d_in[7];
    const float* bc  = (const float*)d_in[8];
    const float* Wn1 = (const float*)d_in[9];
    const float* bn1 = (const float*)d_in[10];
    const float* Wn2 = (const float*)d_in[11];
    const float* bn2 = (const float*)d_in[12];
    float* out = (float*)d_out;
    const int N = in_sizes[0] / STRIDE;
    const int E = in_sizes[2] / 16;

    const int NODE_SMEM = 36864 * 4;
    cudaFuncSetAttribute(edge_kernel, cudaFuncAttributeMaxDynamicSharedMemorySize, EDGE_SMEM);
    cudaFuncSetAttribute(node_kernel, cudaFuncAttributeMaxDynamicSharedMemorySize, NODE_SMEM);

    zero_kernel<<<1024, 256>>>(N);
    prep_h<<<512, 256>>>(nf, N);
    prep_ef<<<1024, 256>>>(ef, E);
    prep_w1<<<144, 256>>>(We1);
    edge_kernel<<<148, 256, EDGE_SMEM>>>(nf, ei, be1, We2, be2, Wc, bc, N, E);
    node_kernel<<<148, TPB_N, NODE_SMEM>>>(nf, Wn1, bn1, Wn2, bn2, out, N);
}

// round 12
// speedup vs baseline: 2.8467x; 1.0898x over previous
#include <cuda_runtime.h>
#include <cuda_bf16.h>
#include <cstdint>

#define D_H 128
#define STRIDE 131
#define MAXN 50000
#define MAXE 800000

// ---- edge smem (bytes) ----
#define X1H_OFF 0u
#define X1L_OFF 37888u
#define WB_OFF  75776u
#define X2H_OFF 116736u
#define X2L_OFF 134144u
#define W2H_OFF 151552u
#define W2L_OFF 186368u
#define SFI_OFF 221184u
#define SCD_OFF 221696u
#define SCP_OFF 223232u
#define EDGE_SMEM 225280
// ---- node smem (bytes) ----
#define NX1H 0u
#define NX1L 33792u
#define NWB  67584u
#define NX2H 108544u
#define NX2L 125952u
#define NW2H 143360u
#define NW2L 178176u
#define NODE_SMEM 212992

__device__ float g_nbr[MAXN * D_H];
__device__ float g_csum[MAXN * 3];
__device__ float g_cnt[MAXN];
__device__ uint16_t g_h_hi[MAXN * 128];
__device__ uint16_t g_h_lo[MAXN * 128];
__device__ uint16_t g_ef_hi[MAXE * 16];
__device__ uint16_t g_ef_lo[MAXE * 16];
__device__ uint16_t g_W1Th[128 * 288];
__device__ uint16_t g_W1Tl[128 * 288];
__device__ uint16_t g_Wn1Th[128 * 256];
__device__ uint16_t g_Wn1Tl[128 * 256];

__device__ __forceinline__ uint32_t smem_u32(const void* p) {
    uint32_t a;
    asm("{ .reg .u64 t; cvta.to.shared.u64 t, %1; cvt.u32.u64 %0, t; }" : "=r"(a) : "l"(p));
    return a;
}
__device__ __forceinline__ float silu(float x) { return x / (1.0f + __expf(-x)); }
__device__ __forceinline__ void cpa16(uint32_t dst, const void* src) {
    asm volatile("cp.async.ca.shared.global [%0], [%1], 16;" :: "r"(dst), "l"(src));
}
#define CPA_COMMIT() asm volatile("cp.async.commit_group;" ::: "memory")
#define CPA_WAIT0()  asm volatile("cp.async.wait_group 0;" ::: "memory")
#define CPA_WAIT1()  asm volatile("cp.async.wait_group 1;" ::: "memory")
__device__ __forceinline__ void sts16(uint32_t a, uint16_t v) { asm volatile("st.shared.u16 [%0], %1;" :: "r"(a), "h"(v)); }
__device__ __forceinline__ void sts32(uint32_t a, uint32_t v) { asm volatile("st.shared.u32 [%0], %1;" :: "r"(a), "r"(v)); }
__device__ __forceinline__ void split_bf16(float v, uint16_t& hi, uint16_t& lo) {
    __nv_bfloat16 h = __float2bfloat16(v);
    __nv_bfloat16 l = __float2bfloat16(v - __bfloat162float(h));
    hi = __bfloat16_as_ushort(h); lo = __bfloat16_as_ushort(l);
}
__device__ __forceinline__ void ldsm4(uint32_t a, uint32_t* r) {
    asm volatile("ldmatrix.sync.aligned.m8n8.x4.shared.b16 {%0,%1,%2,%3}, [%4];"
        : "=r"(r[0]), "=r"(r[1]), "=r"(r[2]), "=r"(r[3]) : "r"(a));
}
__device__ __forceinline__ void mma_bf16(float* d, const uint32_t* a, const uint32_t* b) {
    asm volatile("mma.sync.aligned.m16n8k16.row.col.f32.bf16.bf16.f32 "
        "{%0,%1,%2,%3}, {%4,%5,%6,%7}, {%8,%9}, {%0,%1,%2,%3};"
        : "+f"(d[0]), "+f"(d[1]), "+f"(d[2]), "+f"(d[3])
        : "r"(a[0]), "r"(a[1]), "r"(a[2]), "r"(a[3]), "r"(b[0]), "r"(b[1]));
}

// ---------------- merged prep kernel ----------------
__global__ void prep_all(const float* __restrict__ nf, const float* __restrict__ ef,
                         const float* __restrict__ We1, const float* __restrict__ Wn1,
                         int N, int E) {
    int i = blockIdx.x * blockDim.x + threadIdx.x, s = gridDim.x * blockDim.x;
    float4 z = make_float4(0.f, 0.f, 0.f, 0.f);
    float4* p = (float4*)g_nbr; int n4 = N * D_H / 4;
    for (int k = i; k < n4; k += s) p[k] = z;
    for (int k = i; k < N * 3; k += s) g_csum[k] = 0.f;
    for (int k = i; k < N; k += s) g_cnt[k] = 0.f;
    for (int idx = i; idx < N * 128; idx += s) {
        int n = idx >> 7, j = idx & 127;
        uint16_t h, l; split_bf16(nf[n * STRIDE + 3 + j], h, l);
        g_h_hi[idx] = h; g_h_lo[idx] = l;
    }
    for (int idx = i; idx < E * 16; idx += s) {
        uint16_t h, l; split_bf16(ef[idx], h, l);
        g_ef_hi[idx] = h; g_ef_lo[idx] = l;
    }
    for (int idx = i; idx < 128 * 288; idx += s) {
        int j = idx / 288, k = idx % 288;
        float v = 0.f;
        if (k < 256) v = We1[k * 128 + j];
        else if (k < 272) v = We1[(257 + (k - 256)) * 128 + j];
        else if (k == 272) v = We1[256 * 128 + j];
        uint16_t h, l; split_bf16(v, h, l);
        g_W1Th[idx] = h; g_W1Tl[idx] = l;
    }
    for (int idx = i; idx < 128 * 256; idx += s) {
        int j = idx >> 8, k = idx & 255;
        uint16_t h, l; split_bf16(Wn1[k * 128 + j], h, l);
        g_Wn1Th[idx] = h; g_Wn1Tl[idx] = l;
    }
}

// ---------------- edge kernel ----------------
__device__ __forceinline__ void stage_x1(uint32_t sb, char* smem, int t, int nb,
    const float* __restrict__ nf, const int* __restrict__ first, const int* __restrict__ second, int E)
{
    const int tid = threadIdx.x;
    if (tid < 64) {
        int e = tid, eg = min(t * 64 + e, E - 1);
        int fi = first[eg], si = second[eg];
        ((int*)(smem + SFI_OFF))[nb * 64 + e] = fi;
        float dx = nf[fi * STRIDE] - nf[si * STRIDE];
        float dy = nf[fi * STRIDE + 1] - nf[si * STRIDE + 1];
        float dz = nf[fi * STRIDE + 2] - nf[si * STRIDE + 2];
        float* sc = (float*)(smem + SCD_OFF) + nb * 192;
        sc[e] = dx; sc[64 + e] = dy; sc[128 + e] = dz;
        uint16_t h, l; split_bf16(dx * dx + dy * dy + dz * dz, h, l);
        sts16(sb + X1H_OFF + (uint32_t)((e * 296 + 272) * 2), h);
        sts16(sb + X1L_OFF + (uint32_t)((e * 296 + 272) * 2), l);
    }
    {
        int e = tid & 63, g = (tid >> 6) & 1, mat = tid >> 7;
        int eg = min(t * 64 + e, E - 1);
        const uint16_t* src = (mat ? g_ef_lo : g_ef_hi) + eg * 16 + g * 8;
        cpa16(sb + (mat ? X1L_OFF : X1H_OFF) + (uint32_t)((e * 296 + 256 + g * 8) * 2), src);
    }
    #pragma unroll
    for (int i = 0; i < 16; i++) {
        int idx = tid + i * 256;
        int g = idx & 31, e = (idx >> 5) & 63, mat = idx >> 11;
        int eg = min(t * 64 + e, E - 1);
        int node = (g < 16) ? first[eg] : second[eg];
        const uint16_t* src = (mat ? g_h_lo : g_h_hi) + node * 128 + (g & 15) * 8;
        cpa16(sb + (mat ? X1L_OFF : X1H_OFF) + (uint32_t)((e * 296 + g * 8) * 2), src);
    }
}
__device__ __forceinline__ void stage_w1(uint32_t sb, int c, int wb) {
    const int tid = threadIdx.x;
    #pragma unroll
    for (int i = 0; i < 4; i++) {
        int idx = tid + i * 256;
        int g = idx & 3, j = (idx >> 2) & 127, mat = idx >> 9;
        const uint16_t* src = (mat ? g_W1Tl : g_W1Th) + j * 288 + c * 32 + g * 8;
        cpa16(sb + WB_OFF + (uint32_t)(wb * 20480 + mat * 10240 + (j * 40 + g * 8) * 2), src);
    }
}

__global__ void __launch_bounds__(256, 1) edge_kernel(
    const float* __restrict__ nf, const int* __restrict__ ei,
    const float* __restrict__ be1, const float* __restrict__ We2, const float* __restrict__ be2,
    const float* __restrict__ Wc, const float* __restrict__ bc, int N, int E)
{
    extern __shared__ char smem[];
    const uint32_t sb = smem_u32(smem);
    const int tid = threadIdx.x, w = tid >> 5, lane = tid & 31;
    const int* first = ei;
    const int* second = ei + E;
    int* sfi = (int*)(smem + SFI_OFF);
    float* scp = (float*)(smem + SCP_OFF);

    for (int idx = tid; idx < 64 * 15; idx += 256) {
        int e = idx / 15, c = 273 + idx % 15;
        sts16(sb + X1H_OFF + (uint32_t)((e * 296 + c) * 2), 0);
        sts16(sb + X1L_OFF + (uint32_t)((e * 296 + c) * 2), 0);
    }
    for (int idx = tid; idx < 128 * 128; idx += 256) {
        int k = idx >> 7, j = idx & 127;
        uint16_t h, l; split_bf16(We2[k * 128 + j], h, l);
        sts16(sb + W2H_OFF + (uint32_t)((j * 136 + k) * 2), h);
        sts16(sb + W2L_OFF + (uint32_t)((j * 136 + k) * 2), l);
    }

    const int j1 = 16 * w + (lane >> 2), j2 = j1 + 8;
    const float b1a = be1[j1], b1b = be1[j2];
    const float b2a = be2[j1], b2b = be2[j2];
    const float wc1 = Wc[j1], wc2 = Wc[j2];
    const float bcv = bc[0];

    const int r_a = (lane & 7) + ((lane >> 3) & 1) * 8;
    const int kk_a = ((lane >> 4) & 1) * 8;
    const uint32_t aoff1 = (uint32_t)(((16 * w + r_a) * 40 + kk_a) * 2);
    const uint32_t aoff2 = (uint32_t)(((16 * w + r_a) * 136 + kk_a) * 2);
    const int e_l = (lane & 7) + (lane >> 4) * 8, khalf = (lane >> 3) & 1;
    const uint32_t boff4_1 = (uint32_t)((e_l * 296 + khalf * 8) * 2);
    const uint32_t boff4_2 = (uint32_t)((e_l * 136 + khalf * 8) * 2);

    const int ntiles = (E + 63) / 64;
    int buf = 0;
    __syncthreads();
    if ((int)blockIdx.x < ntiles) {
        stage_x1(sb, smem, blockIdx.x, 0, nf, first, second, E);
        stage_w1(sb, 0, 0);
        CPA_COMMIT();
    }

    for (int t = blockIdx.x; t < ntiles; t += gridDim.x, buf ^= 1) {
        CPA_WAIT0();
        __syncthreads();

        float acc[8][4];
        #pragma unroll
        for (int n = 0; n < 8; n++) { acc[n][0] = b1a; acc[n][1] = b1a; acc[n][2] = b1b; acc[n][3] = b1b; }

        for (int c = 0; c < 9; c++) {
            if (c < 8) { stage_w1(sb, c + 1, (c + 1) & 1); CPA_COMMIT(); CPA_WAIT1(); }
            else CPA_WAIT0();
            __syncthreads();
            #pragma unroll
            for (int s = 0; s < 2; s++) {
                uint32_t ah[4], al[4];
                uint32_t aB = sb + WB_OFF + (uint32_t)((c & 1) * 20480) + aoff1 + (uint32_t)(s * 32);
                ldsm4(aB, ah);
                ldsm4(aB + 10240u, al);
                uint32_t bB = sb + X1H_OFF + boff4_1 + (uint32_t)((c * 32 + s * 16) * 2);
                #pragma unroll
                for (int p = 0; p < 4; p++) {
                    uint32_t bh[4], bl[4];
                    ldsm4(bB + (uint32_t)(p * 9472), bh);
                    ldsm4(bB + (X1L_OFF - X1H_OFF) + (uint32_t)(p * 9472), bl);
                    mma_bf16(acc[2 * p], ah, bh);     mma_bf16(acc[2 * p], ah, bl);     mma_bf16(acc[2 * p], al, bh);
                    mma_bf16(acc[2 * p + 1], ah, bh + 2); mma_bf16(acc[2 * p + 1], ah, bl + 2); mma_bf16(acc[2 * p + 1], al, bh + 2);
                }
            }
            __syncthreads();
        }

        int tn = t + gridDim.x;
        if (tn < ntiles) {
            stage_x1(sb, smem, tn, buf ^ 1, nf, first, second, E);
            stage_w1(sb, 0, 0);
            CPA_COMMIT();
        }

        #pragma unroll
        for (int n = 0; n < 8; n++) {
            int e0 = 8 * n + 2 * (lane & 3);
            float v[4] = { silu(acc[n][0]), silu(acc[n][1]), silu(acc[n][2]), silu(acc[n][3]) };
            const int ee[4] = { e0, e0 + 1, e0, e0 + 1 };
            const int jj[4] = { j1, j1, j2, j2 };
            #pragma unroll
            for (int q = 0; q < 4; q++) {
                uint16_t h, l; split_bf16(v[q], h, l);
                uint32_t o = (uint32_t)((ee[q] * 136 + jj[q]) * 2);
                sts16(sb + X2H_OFF + o, h);
                sts16(sb + X2L_OFF + o, l);
            }
        }
        __syncthreads();

        float a2[8][4];
        #pragma unroll
        for (int n = 0; n < 8; n++) { a2[n][0] = b2a; a2[n][1] = b2a; a2[n][2] = b2b; a2[n][3] = b2b; }
        #pragma unroll
        for (int ks = 0; ks < 8; ks++) {
            uint32_t ah[4], al[4];
            ldsm4(sb + W2H_OFF + aoff2 + (uint32_t)(ks * 32), ah);
            ldsm4(sb + W2L_OFF + aoff2 + (uint32_t)(ks * 32), al);
            uint32_t bB = sb + X2H_OFF + boff4_2 + (uint32_t)(ks * 32);
            #pragma unroll
            for (int p = 0; p < 4; p++) {
                uint32_t bh[4], bl[4];
                ldsm4(bB + (uint32_t)(p * 4352), bh);
                ldsm4(bB + (X2L_OFF - X2H_OFF) + (uint32_t)(p * 4352), bl);
                mma_bf16(a2[2 * p], ah, bh);     mma_bf16(a2[2 * p], ah, bl);     mma_bf16(a2[2 * p], al, bh);
                mma_bf16(a2[2 * p + 1], ah, bh + 2); mma_bf16(a2[2 * p + 1], ah, bl + 2); mma_bf16(a2[2 * p + 1], al, bh + 2);
            }
        }

        #pragma unroll
        for (int n = 0; n < 8; n++) {
            int e0 = 8 * n + 2 * (lane & 3);
            float m0 = silu(a2[n][0]), m1 = silu(a2[n][1]), m2 = silu(a2[n][2]), m3 = silu(a2[n][3]);
            int ge0 = t * 64 + e0;
            if (ge0 < E) {
                int f0 = sfi[buf * 64 + e0];
                atomicAdd(&g_nbr[f0 * 128 + j1], m0);
                atomicAdd(&g_nbr[f0 * 128 + j2], m2);
            }
            if (ge0 + 1 < E) {
                int f1 = sfi[buf * 64 + e0 + 1];
                atomicAdd(&g_nbr[f1 * 128 + j1], m1);
                atomicAdd(&g_nbr[f1 * 128 + j2], m3);
            }
            float p0 = m0 * wc1 + m2 * wc2, p1 = m1 * wc1 + m3 * wc2;
            p0 += __shfl_xor_sync(~0u, p0, 4);  p1 += __shfl_xor_sync(~0u, p1, 4);
            p0 += __shfl_xor_sync(~0u, p0, 8);  p1 += __shfl_xor_sync(~0u, p1, 8);
            p0 += __shfl_xor_sync(~0u, p0, 16); p1 += __shfl_xor_sync(~0u, p1, 16);
            if ((lane >> 2) == 0) { scp[w * 64 + e0] = p0; scp[w * 64 + e0 + 1] = p1; }
        }
        __syncthreads();
        if (tid < 64 && t * 64 + tid < E) {
            int e = tid, fi = sfi[buf * 64 + e];
            float c = bcv;
            #pragma unroll
            for (int k2 = 0; k2 < 8; k2++) c += scp[k2 * 64 + e];
            float* sc = (float*)(smem + SCD_OFF) + buf * 192;
            atomicAdd(&g_csum[fi * 3 + 0], sc[e] * c);
            atomicAdd(&g_csum[fi * 3 + 1], sc[64 + e] * c);
            atomicAdd(&g_csum[fi * 3 + 2], sc[128 + e] * c);
            atomicAdd(&g_cnt[fi], 1.0f);
        }
        __syncthreads();
    }
}

// ---------------- node kernel (warp MMA) ----------------
__device__ __forceinline__ void nstage_x1(uint32_t sb, int t, int N) {
    const int tid = threadIdx.x;
    // h -> cols 0..127 via cpa16
    #pragma unroll
    for (int i = 0; i < 8; i++) {
        int idx = tid + i * 256;
        int g = idx & 15, n = (idx >> 4) & 63, mat = idx >> 10;
        int ng = min(t * 64 + n, N - 1);
        const uint16_t* src = (mat ? g_h_lo : g_h_hi) + ng * 128 + g * 8;
        cpa16(sb + (mat ? NX1L : NX1H) + (uint32_t)((n * 264 + g * 8) * 2), src);
    }
    // nbr -> cols 128..255 (split inline, float4 loads)
    #pragma unroll
    for (int i = 0; i < 8; i++) {
        int idx = tid + i * 256;             // 2048 float4 slots = 64n x 32
        int q4 = idx & 31, n = idx >> 5;
        int ng = min(t * 64 + n, N - 1);
        float4 v = *(const float4*)(g_nbr + ng * 128 + q4 * 4);
        uint16_t h0, l0, h1, l1, h2, l2, h3, l3;
        split_bf16(v.x, h0, l0); split_bf16(v.y, h1, l1);
        split_bf16(v.z, h2, l2); split_bf16(v.w, h3, l3);
        uint32_t o = (uint32_t)((n * 264 + 128 + q4 * 4) * 2);
        sts32(sb + NX1H + o, ((uint32_t)h1 << 16) | h0);
        sts32(sb + NX1H + o + 4, ((uint32_t)h3 << 16) | h2);
        sts32(sb + NX1L + o, ((uint32_t)l1 << 16) | l0);
        sts32(sb + NX1L + o + 4, ((uint32_t)l3 << 16) | l2);
    }
}
__device__ __forceinline__ void nstage_w1(uint32_t sb, int c, int wb) {
    const int tid = threadIdx.x;
    #pragma unroll
    for (int i = 0; i < 4; i++) {
        int idx = tid + i * 256;
        int g = idx & 3, j = (idx >> 2) & 127, mat = idx >> 9;
        const uint16_t* src = (mat ? g_Wn1Tl : g_Wn1Th) + j * 256 + c * 32 + g * 8;
        cpa16(sb + NWB + (uint32_t)(wb * 20480 + mat * 10240 + (j * 40 + g * 8) * 2), src);
    }
}

__global__ void __launch_bounds__(256, 1) node_kernel(
    const float* __restrict__ nf,
    const float* __restrict__ bn1, const float* __restrict__ Wn2, const float* __restrict__ bn2,
    float* __restrict__ out, int N)
{
    extern __shared__ char smem[];
    const uint32_t sb = smem_u32(smem);
    const int tid = threadIdx.x, w = tid >> 5, lane = tid & 31;

    for (int idx = tid; idx < 128 * 128; idx += 256) {
        int k = idx >> 7, j = idx & 127;
        uint16_t h, l; split_bf16(Wn2[k * 128 + j], h, l);
        sts16(sb + NW2H + (uint32_t)((j * 136 + k) * 2), h);
        sts16(sb + NW2L + (uint32_t)((j * 136 + k) * 2), l);
    }
    const int j1 = 16 * w + (lane >> 2), j2 = j1 + 8;
    const float b1a = bn1[j1], b1b = bn1[j2];
    const float b2a = bn2[j1], b2b = bn2[j2];

    const int r_a = (lane & 7) + ((lane >> 3) & 1) * 8;
    const int kk_a = ((lane >> 4) & 1) * 8;
    const uint32_t aoff1 = (uint32_t)(((16 * w + r_a) * 40 + kk_a) * 2);
    const uint32_t aoff2 = (uint32_t)(((16 * w + r_a) * 136 + kk_a) * 2);
    const int e_l = (lane & 7) + (lane >> 4) * 8, khalf = (lane >> 3) & 1;
    const uint32_t boff4_1 = (uint32_t)((e_l * 264 + khalf * 8) * 2);
    const uint32_t boff4_2 = (uint32_t)((e_l * 136 + khalf * 8) * 2);

    const int ntiles = (N + 63) / 64;
    __syncthreads();
    if ((int)blockIdx.x < ntiles) {
        nstage_x1(sb, blockIdx.x, N);
        nstage_w1(sb, 0, 0);
        CPA_COMMIT();
    }

    for (int t = blockIdx.x; t < ntiles; t += gridDim.x) {
        CPA_WAIT0();
        __syncthreads();

        float acc[8][4];
        #pragma unroll
        for (int n = 0; n < 8; n++) { acc[n][0] = b1a; acc[n][1] = b1a; acc[n][2] = b1b; acc[n][3] = b1b; }

        for (int c = 0; c < 8; c++) {
            if (c < 7) { nstage_w1(sb, c + 1, (c + 1) & 1); CPA_COMMIT(); CPA_WAIT1(); }
            else CPA_WAIT0();
            __syncthreads();
            #pragma unroll
            for (int s = 0; s < 2; s++) {
                uint32_t ah[4], al[4];
                uint32_t aB = sb + NWB + (uint32_t)((c & 1) * 20480) + aoff1 + (uint32_t)(s * 32);
                ldsm4(aB, ah);
                ldsm4(aB + 10240u, al);
                uint32_t bB = sb + NX1H + boff4_1 + (uint32_t)((c * 32 + s * 16) * 2);
                #pragma unroll
                for (int p = 0; p < 4; p++) {
                    uint32_t bh[4], bl[4];
                    ldsm4(bB + (uint32_t)(p * 8448), bh);
                    ldsm4(bB + (NX1L - NX1H) + (uint32_t)(p * 8448), bl);
                    mma_bf16(acc[2 * p], ah, bh);     mma_bf16(acc[2 * p], ah, bl);     mma_bf16(acc[2 * p], al, bh);
                    mma_bf16(acc[2 * p + 1], ah, bh + 2); mma_bf16(acc[2 * p + 1], ah, bl + 2); mma_bf16(acc[2 * p + 1], al, bh + 2);
                }
            }
            __syncthreads();
        }

        // epi1: silu -> X2 split
        #pragma unroll
        for (int n = 0; n < 8; n++) {
            int e0 = 8 * n + 2 * (lane & 3);
            float v[4] = { silu(acc[n][0]), silu(acc[n][1]), silu(acc[n][2]), silu(acc[n][3]) };
            const int ee[4] = { e0, e0 + 1, e0, e0 + 1 };
            const int jj[4] = { j1, j1, j2, j2 };
            #pragma unroll
            for (int q = 0; q < 4; q++) {
                uint16_t h, l; split_bf16(v[q], h, l);
                uint32_t o = (uint32_t)((ee[q] * 136 + jj[q]) * 2);
                sts16(sb + NX2H + o, h);
                sts16(sb + NX2L + o, l);
            }
        }
        __syncthreads();

        // prefetch next tile X1 + w chunk0 (overlaps layer 2)
        int tn = t + gridDim.x;
        if (tn < ntiles) {
            nstage_x1(sb, tn, N);
            nstage_w1(sb, 0, 0);
            CPA_COMMIT();
        }

        float a2[8][4];
        #pragma unroll
        for (int n = 0; n < 8; n++) { a2[n][0] = b2a; a2[n][1] = b2a; a2[n][2] = b2b; a2[n][3] = b2b; }
        #pragma unroll
        for (int ks = 0; ks < 8; ks++) {
            uint32_t ah[4], al[4];
            ldsm4(sb + NW2H + aoff2 + (uint32_t)(ks * 32), ah);
            ldsm4(sb + NW2L + aoff2 + (uint32_t)(ks * 32), al);
            uint32_t bB = sb + NX2H + boff4_2 + (uint32_t)(ks * 32);
            #pragma unroll
            for (int p = 0; p < 4; p++) {
                uint32_t bh[4], bl[4];
                ldsm4(bB + (uint32_t)(p * 4352), bh);
                ldsm4(bB + (NX2L - NX2H) + (uint32_t)(p * 4352), bl);
                mma_bf16(a2[2 * p], ah, bh);     mma_bf16(a2[2 * p], ah, bl);     mma_bf16(a2[2 * p], al, bh);
                mma_bf16(a2[2 * p + 1], ah, bh + 2); mma_bf16(a2[2 * p + 1], ah, bl + 2); mma_bf16(a2[2 * p + 1], al, bh + 2);
            }
        }

        // epi2: direct stores to out
        #pragma unroll
        for (int n = 0; n < 8; n++) {
            int e0 = 8 * n + 2 * (lane & 3);
            int n0g = t * 64 + e0;
            if (n0g < N) {
                out[n0g * STRIDE + 3 + j1] = a2[n][0];
                out[n0g * STRIDE + 3 + j2] = a2[n][2];
            }
            if (n0g + 1 < N) {
                out[(n0g + 1) * STRIDE + 3 + j1] = a2[n][1];
                out[(n0g + 1) * STRIDE + 3 + j2] = a2[n][3];
            }
        }
        if (tid < 64) {
            int n = t * 64 + tid;
            if (n < N) {
                float inv = 1.0f / fmaxf(g_cnt[n], 1.0f);
                out[n * STRIDE + 0] = nf[n * STRIDE + 0] + g_csum[n * 3 + 0] * inv;
                out[n * STRIDE + 1] = nf[n * STRIDE + 1] + g_csum[n * 3 + 1] * inv;
                out[n * STRIDE + 2] = nf[n * STRIDE + 2] + g_csum[n * 3 + 2] * inv;
            }
        }
        __syncthreads();
    }
}

extern "C" void kernel_launch(void* const* d_in, const int* in_sizes, int n_in,
                              void* d_out, int out_size) {
    const float* nf  = (const float*)d_in[0];
    const int*   ei  = (const int*)d_in[1];
    const float* ef  = (const float*)d_in[2];
    const float* We1 = (const float*)d_in[3];
    const float* be1 = (const float*)d_in[4];
    const float* We2 = (const float*)d_in[5];
    const float* be2 = (const float*)d_in[6];
    const float* Wc  = (const float*)d_in[7];
    const float* bc  = (const float*)d_in[8];
    const float* Wn1 = (const float*)d_in[9];
    const float* bn1 = (const float*)d_in[10];
    const float* Wn2 = (const float*)d_in[11];
    const float* bn2 = (const float*)d_in[12];
    float* out = (float*)d_out;
    const int N = in_sizes[0] / STRIDE;
    const int E = in_sizes[2] / 16;

    cudaFuncSetAttribute(edge_kernel, cudaFuncAttributeMaxDynamicSharedMemorySize, EDGE_SMEM);
    cudaFuncSetAttribute(node_kernel, cudaFuncAttributeMaxDynamicSharedMemorySize, NODE_SMEM);

    prep_all<<<1024, 256>>>(nf, ef, We1, Wn1, N, E);
    edge_kernel<<<148, 256, EDGE_SMEM>>>(nf, ei, be1, We2, be2, Wc, bc, N, E);
    node_kernel<<<148, 256, NODE_SMEM>>>(nf, bn1, Wn2, bn2, out, N);
}

// round 15
// speedup vs baseline: 3.5332x; 1.2412x over previous
#include <cuda_runtime.h>
#include <cuda_bf16.h>
#include <cstdint>

#define D_H 128
#define STRIDE 131
#define MAXN 50000
#define MAXE 800000

// ---- edge smem (bytes) ----
#define W1H_OFF 0u          // 128x296 halfs = 75776
#define W1L_OFF 75776u
#define X1H_OFF 151552u     // 64x296 halfs = 37888 (X2 overlays, stride 136)
#define X1L_OFF 189440u
#define SFI_OFF 227328u     // int[2][64]
#define SCD_OFF 227840u     // float[2][192]
#define SCP_OFF 229376u     // float[8][64]
#define EDGE_SMEM 231424
// ---- node smem (bytes) ----
#define NW1H 0u             // 128x264 halfs = 67584
#define NW1L 67584u
#define NX1H 135168u        // 64x264 = 33792, padded region 34816 (W2 scratch + X2 overlay)
#define NX1L 169984u
#define NODE_SMEM 204800

__device__ float g_nbr[MAXN * D_H];
__device__ float g_csum[MAXN * 3];
__device__ float g_cnt[MAXN];
__device__ uint16_t g_h_hi[MAXN * 128];
__device__ uint16_t g_h_lo[MAXN * 128];
__device__ uint16_t g_ef_hi[MAXE * 16];
__device__ uint16_t g_ef_lo[MAXE * 16];
__device__ uint16_t g_W1Th[128 * 288];
__device__ uint16_t g_W1Tl[128 * 288];
__device__ uint16_t g_Wn1Th[128 * 256];
__device__ uint16_t g_Wn1Tl[128 * 256];

__device__ __forceinline__ uint32_t smem_u32(const void* p) {
    uint32_t a;
    asm("{ .reg .u64 t; cvta.to.shared.u64 t, %1; cvt.u32.u64 %0, t; }" : "=r"(a) : "l"(p));
    return a;
}
__device__ __forceinline__ float silu(float x) { return x / (1.0f + __expf(-x)); }
__device__ __forceinline__ void cpa16(uint32_t dst, const void* src) {
    asm volatile("cp.async.ca.shared.global [%0], [%1], 16;" :: "r"(dst), "l"(src));
}
#define CPA_COMMIT() asm volatile("cp.async.commit_group;" ::: "memory")
#define CPA_WAIT0()  asm volatile("cp.async.wait_group 0;" ::: "memory")
__device__ __forceinline__ void sts16(uint32_t a, uint16_t v) { asm volatile("st.shared.u16 [%0], %1;" :: "r"(a), "h"(v)); }
__device__ __forceinline__ void sts32(uint32_t a, uint32_t v) { asm volatile("st.shared.u32 [%0], %1;" :: "r"(a), "r"(v)); }
__device__ __forceinline__ void split_bf16(float v, uint16_t& hi, uint16_t& lo) {
    __nv_bfloat16 h = __float2bfloat16(v);
    __nv_bfloat16 l = __float2bfloat16(v - __bfloat162float(h));
    hi = __bfloat16_as_ushort(h); lo = __bfloat16_as_ushort(l);
}
__device__ __forceinline__ void ldsm4(uint32_t a, uint32_t* r) {
    asm volatile("ldmatrix.sync.aligned.m8n8.x4.shared.b16 {%0,%1,%2,%3}, [%4];"
        : "=r"(r[0]), "=r"(r[1]), "=r"(r[2]), "=r"(r[3]) : "r"(a));
}
__device__ __forceinline__ void mma_bf16(float* d, const uint32_t* a, const uint32_t* b) {
    asm volatile("mma.sync.aligned.m16n8k16.row.col.f32.bf16.bf16.f32 "
        "{%0,%1,%2,%3}, {%4,%5,%6,%7}, {%8,%9}, {%0,%1,%2,%3};"
        : "+f"(d[0]), "+f"(d[1]), "+f"(d[2]), "+f"(d[3])
        : "r"(a[0]), "r"(a[1]), "r"(a[2]), "r"(a[3]), "r"(b[0]), "r"(b[1]));
}

// ---------------- merged prep kernel ----------------
__global__ void prep_all(const float* __restrict__ nf, const float* __restrict__ ef,
                         const float* __restrict__ We1, const float* __restrict__ Wn1,
                         int N, int E) {
    int i = blockIdx.x * blockDim.x + threadIdx.x, s = gridDim.x * blockDim.x;
    float4 z = make_float4(0.f, 0.f, 0.f, 0.f);
    float4* p = (float4*)g_nbr; int n4 = N * D_H / 4;
    for (int k = i; k < n4; k += s) p[k] = z;
    for (int k = i; k < N * 3; k += s) g_csum[k] = 0.f;
    for (int k = i; k < N; k += s) g_cnt[k] = 0.f;
    for (int idx = i; idx < N * 128; idx += s) {
        int n = idx >> 7, j = idx & 127;
        uint16_t h, l; split_bf16(nf[n * STRIDE + 3 + j], h, l);
        g_h_hi[idx] = h; g_h_lo[idx] = l;
    }
    for (int idx = i; idx < E * 16; idx += s) {
        uint16_t h, l; split_bf16(ef[idx], h, l);
        g_ef_hi[idx] = h; g_ef_lo[idx] = l;
    }
    for (int idx = i; idx < 128 * 288; idx += s) {
        int j = idx / 288, k = idx % 288;
        float v = 0.f;
        if (k < 256) v = We1[k * 128 + j];
        else if (k < 272) v = We1[(257 + (k - 256)) * 128 + j];
        else if (k == 272) v = We1[256 * 128 + j];
        uint16_t h, l; split_bf16(v, h, l);
        g_W1Th[idx] = h; g_W1Tl[idx] = l;
    }
    for (int idx = i; idx < 128 * 256; idx += s) {
        int j = idx >> 8, k = idx & 255;
        uint16_t h, l; split_bf16(Wn1[k * 128 + j], h, l);
        g_Wn1Th[idx] = h; g_Wn1Tl[idx] = l;
    }
}

// ---------------- edge kernel ----------------
__device__ __forceinline__ void stage_x1(uint32_t sb, char* smem, int t, int nb,
    const float* __restrict__ nf, const int* __restrict__ first, const int* __restrict__ second, int E)
{
    const int tid = threadIdx.x;
    if (tid < 64) {
        int e = tid, eg = min(t * 64 + e, E - 1);
        int fi = first[eg], si = second[eg];
        ((int*)(smem + SFI_OFF))[nb * 64 + e] = fi;
        float dx = nf[fi * STRIDE] - nf[si * STRIDE];
        float dy = nf[fi * STRIDE + 1] - nf[si * STRIDE + 1];
        float dz = nf[fi * STRIDE + 2] - nf[si * STRIDE + 2];
        float* sc = (float*)(smem + SCD_OFF) + nb * 192;
        sc[e] = dx; sc[64 + e] = dy; sc[128 + e] = dz;
        uint16_t h, l; split_bf16(dx * dx + dy * dy + dz * dz, h, l);
        sts16(sb + X1H_OFF + (uint32_t)((e * 296 + 272) * 2), h);
        sts16(sb + X1L_OFF + (uint32_t)((e * 296 + 272) * 2), l);
    }
    {
        int e = tid & 63, g = (tid >> 6) & 1, mat = tid >> 7;
        int eg = min(t * 64 + e, E - 1);
        const uint16_t* src = (mat ? g_ef_lo : g_ef_hi) + eg * 16 + g * 8;
        cpa16(sb + (mat ? X1L_OFF : X1H_OFF) + (uint32_t)((e * 296 + 256 + g * 8) * 2), src);
    }
    #pragma unroll
    for (int i = 0; i < 16; i++) {
        int idx = tid + i * 256;
        int g = idx & 31, e = (idx >> 5) & 63, mat = idx >> 11;
        int eg = min(t * 64 + e, E - 1);
        int node = (g < 16) ? first[eg] : second[eg];
        const uint16_t* src = (mat ? g_h_lo : g_h_hi) + node * 128 + (g & 15) * 8;
        cpa16(sb + (mat ? X1L_OFF : X1H_OFF) + (uint32_t)((e * 296 + g * 8) * 2), src);
    }
}

__global__ void __launch_bounds__(256, 1) edge_kernel(
    const float* __restrict__ nf, const int* __restrict__ ei,
    const float* __restrict__ be1, const float* __restrict__ We2, const float* __restrict__ be2,
    const float* __restrict__ Wc, const float* __restrict__ bc, int N, int E)
{
    extern __shared__ char smem[];
    const uint32_t sb = smem_u32(smem);
    const int tid = threadIdx.x, w = tid >> 5, lane = tid & 31;
    const int* first = ei;
    const int* second = ei + E;
    int* sfi = (int*)(smem + SFI_OFF);
    float* scp = (float*)(smem + SCP_OFF);

    const int j1 = 16 * w + (lane >> 2), j2 = j1 + 8;
    const float b1a = be1[j1], b1b = be1[j2];
    const float b2a = be2[j1], b2b = be2[j2];
    const float wc1 = Wc[j1], wc2 = Wc[j2];
    const float bcv = bc[0];

    const int r_a = (lane & 7) + ((lane >> 3) & 1) * 8;
    const int kk_a = ((lane >> 4) & 1) * 8;
    const uint32_t aoffW1 = (uint32_t)(((16 * w + r_a) * 296 + kk_a) * 2);
    const uint32_t aoff136 = (uint32_t)(((16 * w + r_a) * 136 + kk_a) * 2);
    const int e_l = (lane & 7) + (lane >> 4) * 8, khalf = (lane >> 3) & 1;
    const uint32_t boff4_1 = (uint32_t)((e_l * 296 + khalf * 8) * 2);
    const uint32_t boff4_2 = (uint32_t)((e_l * 136 + khalf * 8) * 2);

    // --- startup: W2 split into X1 scratch, ldsm into registers ---
    for (int idx = tid; idx < 128 * 128; idx += 256) {
        int k = idx >> 7, j = idx & 127;
        uint16_t h, l; split_bf16(We2[k * 128 + j], h, l);
        sts16(sb + X1H_OFF + (uint32_t)((j * 136 + k) * 2), h);
        sts16(sb + X1L_OFF + (uint32_t)((j * 136 + k) * 2), l);
    }
    __syncthreads();
    uint32_t w2h[8][4], w2l[8][4];
    #pragma unroll
    for (int ks = 0; ks < 8; ks++) {
        ldsm4(sb + X1H_OFF + aoff136 + (uint32_t)(ks * 32), w2h[ks]);
        ldsm4(sb + X1L_OFF + aoff136 + (uint32_t)(ks * 32), w2l[ks]);
    }
    __syncthreads();
    // zero X1 pad cols 273..287
    for (int idx = tid; idx < 64 * 15; idx += 256) {
        int e = idx / 15, c = 273 + idx % 15;
        sts16(sb + X1H_OFF + (uint32_t)((e * 296 + c) * 2), 0);
        sts16(sb + X1L_OFF + (uint32_t)((e * 296 + c) * 2), 0);
    }
    // stage resident W1 (cols 0..287 from 288-wide tables) + first X1
    for (int idx = tid; idx < 128 * 36 * 2; idx += 256) {
        int g = idx % 36, j = (idx / 36) & 127, mat = idx / (36 * 128);
        const uint16_t* src = (mat ? g_W1Tl : g_W1Th) + j * 288 + g * 8;
        cpa16(sb + (mat ? W1L_OFF : W1H_OFF) + (uint32_t)((j * 296 + g * 8) * 2), src);
    }
    const int ntiles = (E + 63) / 64;
    if ((int)blockIdx.x < ntiles)
        stage_x1(sb, smem, blockIdx.x, 0, nf, first, second, E);
    CPA_COMMIT();

    int buf = 0;
    for (int t = blockIdx.x; t < ntiles; t += gridDim.x, buf ^= 1) {
        CPA_WAIT0();
        __syncthreads();

        float acc[8][4];
        #pragma unroll
        for (int n = 0; n < 8; n++) { acc[n][0] = b1a; acc[n][1] = b1a; acc[n][2] = b1b; acc[n][3] = b1b; }

        // ---- layer 1: 18 k-steps, no syncs (W1/X1 read-only) ----
        #pragma unroll 2
        for (int kc = 0; kc < 18; kc++) {
            uint32_t ah[4], al[4];
            uint32_t aB = sb + aoffW1 + (uint32_t)(kc * 32);
            ldsm4(aB + W1H_OFF, ah);
            ldsm4(aB + W1L_OFF, al);
            uint32_t bB = sb + X1H_OFF + boff4_1 + (uint32_t)(kc * 32);
            #pragma unroll
            for (int p = 0; p < 4; p++) {
                uint32_t bh[4], bl[4];
                ldsm4(bB + (uint32_t)(p * 9472), bh);
                ldsm4(bB + (X1L_OFF - X1H_OFF) + (uint32_t)(p * 9472), bl);
                mma_bf16(acc[2 * p], ah, bh);     mma_bf16(acc[2 * p], ah, bl);     mma_bf16(acc[2 * p], al, bh);
                mma_bf16(acc[2 * p + 1], ah, bh + 2); mma_bf16(acc[2 * p + 1], ah, bl + 2); mma_bf16(acc[2 * p + 1], al, bh + 2);
            }
        }
        __syncthreads();   // all warps done reading X1 before X2 overlay

        // ---- epi1: silu -> X2 (overlay on X1 region, stride 136) ----
        #pragma unroll
        for (int n = 0; n < 8; n++) {
            int e0 = 8 * n + 2 * (lane & 3);
            float v[4] = { silu(acc[n][0]), silu(acc[n][1]), silu(acc[n][2]), silu(acc[n][3]) };
            const int ee[4] = { e0, e0 + 1, e0, e0 + 1 };
            const int jj[4] = { j1, j1, j2, j2 };
            #pragma unroll
            for (int q = 0; q < 4; q++) {
                uint16_t h, l; split_bf16(v[q], h, l);
                uint32_t o = (uint32_t)((ee[q] * 136 + jj[q]) * 2);
                sts16(sb + X1H_OFF + o, h);
                sts16(sb + X1L_OFF + o, l);
            }
        }
        __syncthreads();

        // ---- layer 2: W2 from registers ----
        float a2[8][4];
        #pragma unroll
        for (int n = 0; n < 8; n++) { a2[n][0] = b2a; a2[n][1] = b2a; a2[n][2] = b2b; a2[n][3] = b2b; }
        #pragma unroll
        for (int ks = 0; ks < 8; ks++) {
            uint32_t bB = sb + X1H_OFF + boff4_2 + (uint32_t)(ks * 32);
            #pragma unroll
            for (int p = 0; p < 4; p++) {
                uint32_t bh[4], bl[4];
                ldsm4(bB + (uint32_t)(p * 4352), bh);
                ldsm4(bB + (X1L_OFF - X1H_OFF) + (uint32_t)(p * 4352), bl);
                mma_bf16(a2[2 * p], w2h[ks], bh);     mma_bf16(a2[2 * p], w2h[ks], bl);     mma_bf16(a2[2 * p], w2l[ks], bh);
                mma_bf16(a2[2 * p + 1], w2h[ks], bh + 2); mma_bf16(a2[2 * p + 1], w2h[ks], bl + 2); mma_bf16(a2[2 * p + 1], w2l[ks], bh + 2);
            }
        }
        __syncthreads();   // X2 consumed; safe to restage X1

        int tn = t + gridDim.x;
        if (tn < ntiles)
            stage_x1(sb, smem, tn, buf ^ 1, nf, first, second, E);
        CPA_COMMIT();

        // ---- epi2: silu -> atomics + coord gate ----
        #pragma unroll
        for (int n = 0; n < 8; n++) {
            int e0 = 8 * n + 2 * (lane & 3);
            float m0 = silu(a2[n][0]), m1 = silu(a2[n][1]), m2 = silu(a2[n][2]), m3 = silu(a2[n][3]);
            int ge0 = t * 64 + e0;
            if (ge0 < E) {
                int f0 = sfi[buf * 64 + e0];
                atomicAdd(&g_nbr[f0 * 128 + j1], m0);
                atomicAdd(&g_nbr[f0 * 128 + j2], m2);
            }
            if (ge0 + 1 < E) {
                int f1 = sfi[buf * 64 + e0 + 1];
                atomicAdd(&g_nbr[f1 * 128 + j1], m1);
                atomicAdd(&g_nbr[f1 * 128 + j2], m3);
            }
            float p0 = m0 * wc1 + m2 * wc2, p1 = m1 * wc1 + m3 * wc2;
            p0 += __shfl_xor_sync(~0u, p0, 4);  p1 += __shfl_xor_sync(~0u, p1, 4);
            p0 += __shfl_xor_sync(~0u, p0, 8);  p1 += __shfl_xor_sync(~0u, p1, 8);
            p0 += __shfl_xor_sync(~0u, p0, 16); p1 += __shfl_xor_sync(~0u, p1, 16);
            if ((lane >> 2) == 0) { scp[w * 64 + e0] = p0; scp[w * 64 + e0 + 1] = p1; }
        }
        __syncthreads();
        if (tid < 64 && t * 64 + tid < E) {
            int e = tid, fi = sfi[buf * 64 + e];
            float c = bcv;
            #pragma unroll
            for (int k2 = 0; k2 < 8; k2++) c += scp[k2 * 64 + e];
            float* sc = (float*)(smem + SCD_OFF) + buf * 192;
            atomicAdd(&g_csum[fi * 3 + 0], sc[e] * c);
            atomicAdd(&g_csum[fi * 3 + 1], sc[64 + e] * c);
            atomicAdd(&g_csum[fi * 3 + 2], sc[128 + e] * c);
            atomicAdd(&g_cnt[fi], 1.0f);
        }
    }
}

// ---------------- node kernel ----------------
__device__ __forceinline__ void nstage_x1(uint32_t sb, int t, int N) {
    const int tid = threadIdx.x;
    #pragma unroll
    for (int i = 0; i < 8; i++) {
        int idx = tid + i * 256;
        int g = idx & 15, n = (idx >> 4) & 63, mat = idx >> 10;
        int ng = min(t * 64 + n, N - 1);
        const uint16_t* src = (mat ? g_h_lo : g_h_hi) + ng * 128 + g * 8;
        cpa16(sb + (mat ? NX1L : NX1H) + (uint32_t)((n * 264 + g * 8) * 2), src);
    }
    #pragma unroll
    for (int i = 0; i < 8; i++) {
        int idx = tid + i * 256;
        int q4 = idx & 31, n = idx >> 5;
        int ng = min(t * 64 + n, N - 1);
        float4 v = *(const float4*)(g_nbr + ng * 128 + q4 * 4);
        uint16_t h0, l0, h1, l1, h2, l2, h3, l3;
        split_bf16(v.x, h0, l0); split_bf16(v.y, h1, l1);
        split_bf16(v.z, h2, l2); split_bf16(v.w, h3, l3);
        uint32_t o = (uint32_t)((n * 264 + 128 + q4 * 4) * 2);
        sts32(sb + NX1H + o, ((uint32_t)h1 << 16) | h0);
        sts32(sb + NX1H + o + 4, ((uint32_t)h3 << 16) | h2);
        sts32(sb + NX1L + o, ((uint32_t)l1 << 16) | l0);
        sts32(sb + NX1L + o + 4, ((uint32_t)l3 << 16) | l2);
    }
}

__global__ void __launch_bounds__(256, 1) node_kernel(
    const float* __restrict__ nf,
    const float* __restrict__ bn1, const float* __restrict__ Wn2, const float* __restrict__ bn2,
    float* __restrict__ out, int N)
{
    extern __shared__ char smem[];
    const uint32_t sb = smem_u32(smem);
    const int tid = threadIdx.x, w = tid >> 5, lane = tid & 31;

    const int j1 = 16 * w + (lane >> 2), j2 = j1 + 8;
    const float b1a = bn1[j1], b1b = bn1[j2];
    const float b2a = bn2[j1], b2b = bn2[j2];

    const int r_a = (lane & 7) + ((lane >> 3) & 1) * 8;
    const int kk_a = ((lane >> 4) & 1) * 8;
    const uint32_t aoffW1 = (uint32_t)(((16 * w + r_a) * 264 + kk_a) * 2);
    const uint32_t aoff136 = (uint32_t)(((16 * w + r_a) * 136 + kk_a) * 2);
    const int e_l = (lane & 7) + (lane >> 4) * 8, khalf = (lane >> 3) & 1;
    const uint32_t boff4_1 = (uint32_t)((e_l * 264 + khalf * 8) * 2);
    const uint32_t boff4_2 = (uint32_t)((e_l * 136 + khalf * 8) * 2);

    // startup: Wn2 scratch -> registers
    for (int idx = tid; idx < 128 * 128; idx += 256) {
        int k = idx >> 7, j = idx & 127;
        uint16_t h, l; split_bf16(Wn2[k * 128 + j], h, l);
        sts16(sb + NX1H + (uint32_t)((j * 136 + k) * 2), h);
        sts16(sb + NX1L + (uint32_t)((j * 136 + k) * 2), l);
    }
    __syncthreads();
    uint32_t w2h[8][4], w2l[8][4];
    #pragma unroll
    for (int ks = 0; ks < 8; ks++) {
        ldsm4(sb + NX1H + aoff136 + (uint32_t)(ks * 32), w2h[ks]);
        ldsm4(sb + NX1L + aoff136 + (uint32_t)(ks * 32), w2l[ks]);
    }
    __syncthreads();
    // stage resident Wn1 + first X1
    for (int idx = tid; idx < 128 * 32 * 2; idx += 256) {
        int g = idx & 31, j = (idx >> 5) & 127, mat = idx >> 12;
        const uint16_t* src = (mat ? g_Wn1Tl : g_Wn1Th) + j * 256 + g * 8;
        cpa16(sb + (mat ? NW1L : NW1H) + (uint32_t)((j * 264 + g * 8) * 2), src);
    }
    const int ntiles = (N + 63) / 64;
    if ((int)blockIdx.x < ntiles) nstage_x1(sb, blockIdx.x, N);
    CPA_COMMIT();

    for (int t = blockIdx.x; t < ntiles; t += gridDim.x) {
        CPA_WAIT0();
        __syncthreads();

        float acc[8][4];
        #pragma unroll
        for (int n = 0; n < 8; n++) { acc[n][0] = b1a; acc[n][1] = b1a; acc[n][2] = b1b; acc[n][3] = b1b; }

        #pragma unroll 2
        for (int kc = 0; kc < 16; kc++) {
            uint32_t ah[4], al[4];
            uint32_t aB = sb + aoffW1 + (uint32_t)(kc * 32);
            ldsm4(aB + NW1H, ah);
            ldsm4(aB + NW1L, al);
            uint32_t bB = sb + NX1H + boff4_1 + (uint32_t)(kc * 32);
            #pragma unroll
            for (int p = 0; p < 4; p++) {
                uint32_t bh[4], bl[4];
                ldsm4(bB + (uint32_t)(p * 8448), bh);
                ldsm4(bB + (NX1L - NX1H) + (uint32_t)(p * 8448), bl);
                mma_bf16(acc[2 * p], ah, bh);     mma_bf16(acc[2 * p], ah, bl);     mma_bf16(acc[2 * p], al, bh);
                mma_bf16(acc[2 * p + 1], ah, bh + 2); mma_bf16(acc[2 * p + 1], ah, bl + 2); mma_bf16(acc[2 * p + 1], al, bh + 2);
            }
        }
        __syncthreads();

        #pragma unroll
        for (int n = 0; n < 8; n++) {
            int e0 = 8 * n + 2 * (lane & 3);
            float v[4] = { silu(acc[n][0]), silu(acc[n][1]), silu(acc[n][2]), silu(acc[n][3]) };
            const int ee[4] = { e0, e0 + 1, e0, e0 + 1 };
            const int jj[4] = { j1, j1, j2, j2 };
            #pragma unroll
            for (int q = 0; q < 4; q++) {
                uint16_t h, l; split_bf16(v[q], h, l);
                uint32_t o = (uint32_t)((ee[q] * 136 + jj[q]) * 2);
                sts16(sb + NX1H + o, h);
                sts16(sb + NX1L + o, l);
            }
        }
        __syncthreads();

        float a2[8][4];
        #pragma unroll
        for (int n = 0; n < 8; n++) { a2[n][0] = b2a; a2[n][1] = b2a; a2[n][2] = b2b; a2[n][3] = b2b; }
        #pragma unroll
        for (int ks = 0; ks < 8; ks++) {
            uint32_t bB = sb + NX1H + boff4_2 + (uint32_t)(ks * 32);
            #pragma unroll
            for (int p = 0; p < 4; p++) {
                uint32_t bh[4], bl[4];
                ldsm4(bB + (uint32_t)(p * 4352), bh);
                ldsm4(bB + (NX1L - NX1H) + (uint32_t)(p * 4352), bl);
                mma_bf16(a2[2 * p], w2h[ks], bh);     mma_bf16(a2[2 * p], w2h[ks], bl);     mma_bf16(a2[2 * p], w2l[ks], bh);
                mma_bf16(a2[2 * p + 1], w2h[ks], bh + 2); mma_bf16(a2[2 * p + 1], w2h[ks], bl + 2); mma_bf16(a2[2 * p + 1], w2l[ks], bh + 2);
            }
        }
        __syncthreads();   // X2 consumed; safe to restage

        int tn = t + gridDim.x;
        if (tn < ntiles) nstage_x1(sb, tn, N);
        CPA_COMMIT();

        #pragma unroll
        for (int n = 0; n < 8; n++) {
            int e0 = 8 * n + 2 * (lane & 3);
            int n0g = t * 64 + e0;
            if (n0g < N) {
                out[n0g * STRIDE + 3 + j1] = a2[n][0];
                out[n0g * STRIDE + 3 + j2] = a2[n][2];
            }
            if (n0g + 1 < N) {
                out[(n0g + 1) * STRIDE + 3 + j1] = a2[n][1];
                out[(n0g + 1) * STRIDE + 3 + j2] = a2[n][3];
            }
        }
        if (tid < 64) {
            int n = t * 64 + tid;
            if (n < N) {
                float inv = 1.0f / fmaxf(g_cnt[n], 1.0f);
                out[n * STRIDE + 0] = nf[n * STRIDE + 0] + g_csum[n * 3 + 0] * inv;
                out[n * STRIDE + 1] = nf[n * STRIDE + 1] + g_csum[n * 3 + 1] * inv;
                out[n * STRIDE + 2] = nf[n * STRIDE + 2] + g_csum[n * 3 + 2] * inv;
            }
        }
    }
}

extern "C" void kernel_launch(void* const* d_in, const int* in_sizes, int n_in,
                              void* d_out, int out_size) {
    const float* nf  = (const float*)d_in[0];
    const int*   ei  = (const int*)d_in[1];
    const float* ef  = (const float*)d_in[2];
    const float* We1 = (const float*)d_in[3];
    const float* be1 = (const float*)d_in[4];
    const float* We2 = (const float*)d_in[5];
    const float* be2 = (const float*)d_in[6];
    const float* Wc  = (const float*)d_in[7];
    const float* bc  = (const float*)d_in[8];
    const float* Wn1 = (const float*)d_in[9];
    const float* bn1 = (const float*)d_in[10];
    const float* Wn2 = (const float*)d_in[11];
    const float* bn2 = (const float*)d_in[12];
    float* out = (float*)d_out;
    const int N = in_sizes[0] / STRIDE;
    const int E = in_sizes[2] / 16;

    cudaFuncSetAttribute(edge_kernel, cudaFuncAttributeMaxDynamicSharedMemorySize, EDGE_SMEM);
    cudaFuncSetAttribute(node_kernel, cudaFuncAttributeMaxDynamicSharedMemorySize, NODE_SMEM);

    prep_all<<<1024, 256>>>(nf, ef, We1, Wn1, N, E);
    edge_kernel<<<148, 256, EDGE_SMEM>>>(nf, ei, be1, We2, be2, Wc, bc, N, E);
    node_kernel<<<148, 256, NODE_SMEM>>>(nf, bn1, Wn2, bn2, out, N);
}